// round 8
// baseline (speedup 1.0000x reference)
#include <cuda_runtime.h>
#include <cuda_bf16.h>
#include <cstdint>
#include <math.h>

#define H    2048
#define DIN  784
#define DOUT 10
#define NPAD1 896                 // DIN padded to a multiple of 128

// ---------------- scratch (device globals; no allocations allowed) ----------------
__device__ __align__(256) float g_u0[DIN], g_l0[DIN];
__device__ __align__(256) float g_ubL[3 * H], g_lbL[3 * H];
__device__ __align__(256) float g_sus[3 * H], g_sui[3 * H];
__device__ __align__(256) float g_sls[3 * H], g_sli[3 * H];
__device__ __align__(256) float g_pub[3 * H], g_plb[3 * H];
__device__ __align__(256) float g_ub4[DOUT], g_lb4[DOUT];
__device__ __align__(256) float g_rawV[2 * H];                // raw descended values (u | l)
__device__ __align__(256) float g_W0[(long)2 * H * NPAD1];    // final-GEMM fp32 output
__device__ __align__(256) float g_Bias[2 * H];                // running chain bias
// bf16 split operand buffers (ping-pong A) + transposed weights (B)
__device__ __align__(256) __nv_bfloat16 g_Ahi[(long)2 * H * H];
__device__ __align__(256) __nv_bfloat16 g_Alo[(long)2 * H * H];
__device__ __align__(256) __nv_bfloat16 g_Ahi2[(long)2 * H * H];
__device__ __align__(256) __nv_bfloat16 g_Alo2[(long)2 * H * H];
__device__ __align__(256) __nv_bfloat16 g_T1hi[(long)NPAD1 * H], g_T1lo[(long)NPAD1 * H];
__device__ __align__(256) __nv_bfloat16 g_T2hi[(long)H * H],     g_T2lo[(long)H * H];
__device__ __align__(256) __nv_bfloat16 g_T3hi[(long)H * H],     g_T3lo[(long)H * H];

// ---------------- small device helpers ----------------
__device__ __forceinline__ float sigm_(float x) { return 1.0f / (1.0f + expf(-x)); }
__device__ __forceinline__ float spu_(float x) {
    return (x >= 0.0f) ? (x * x - 0.5f) : (sigm_(-x) - 1.0f);
}
__device__ __forceinline__ float warp_reduce(float v) {
#pragma unroll
    for (int o = 16; o > 0; o >>= 1) v += __shfl_down_sync(0xffffffffu, v, o);
    return v;
}
__device__ __forceinline__ uint32_t smem_u32(const void* p) {
    uint32_t a;
    asm("{ .reg .u64 t; cvta.to.shared.u64 t, %1; cvt.u32.u64 %0, t; }" : "=r"(a) : "l"(p));
    return a;
}
__device__ __forceinline__ void cp16(uint32_t dst, const void* src) {
    asm volatile("cp.async.cg.shared.global [%0], [%1], 16;" :: "r"(dst), "l"(src));
}
__device__ __forceinline__ void mma16816(float* d, const uint32_t* a, const uint32_t* b) {
    asm volatile(
        "mma.sync.aligned.m16n8k16.row.col.f32.bf16.bf16.f32 "
        "{%0,%1,%2,%3}, {%4,%5,%6,%7}, {%8,%9}, {%0,%1,%2,%3};"
        : "+f"(d[0]), "+f"(d[1]), "+f"(d[2]), "+f"(d[3])
        : "r"(a[0]), "r"(a[1]), "r"(a[2]), "r"(a[3]), "r"(b[0]), "r"(b[1]));
}
__device__ __forceinline__ __nv_bfloat162 split_hi(float a, float b, float& ra, float& rb) {
    __nv_bfloat16 ha = __float2bfloat16(a), hb = __float2bfloat16(b);
    ra = a - __bfloat162float(ha);
    rb = b - __bfloat162float(hb);
    return __halves2bfloat162(ha, hb);
}

// ---------------- elementwise kernels ----------------
__global__ void k_init_bounds(const float* __restrict__ in, const float* __restrict__ epsp,
                              float* __restrict__ u0, float* __restrict__ l0) {
    int i = blockIdx.x * blockDim.x + threadIdx.x;
    if (i >= DIN) return;
    float e = epsp[0];
    float u = fminf(in[i] + e, 1.0f);
    float l = fmaxf(in[i] - e, 0.0f);
    u0[i] = (u - 0.1307f) / 0.3081f;
    l0[i] = (l - 0.1307f) / 0.3081f;
}

// transpose + bf16 split: T[n][k] = W[k][n]; rows n >= N (padding) are zero.
__global__ void k_transpose_split(const float* __restrict__ W,
                                  __nv_bfloat16* __restrict__ Thi,
                                  __nv_bfloat16* __restrict__ Tlo, int N) {
    __shared__ float t[32][33];
    int n0 = blockIdx.x * 32, k0 = blockIdx.y * 32;
    int tx = threadIdx.x, ty = threadIdx.y;
#pragma unroll
    for (int i = 0; i < 4; i++) {
        int k = k0 + ty + 8 * i;
        int n = n0 + tx;
        t[ty + 8 * i][tx] = (n < N) ? W[(long)k * N + n] : 0.0f;
    }
    __syncthreads();
#pragma unroll
    for (int i = 0; i < 4; i++) {
        int n = n0 + ty + 8 * i;
        int k = k0 + tx;
        float v = t[tx][ty + 8 * i];
        __nv_bfloat16 hi = __float2bfloat16(v);
        __nv_bfloat16 lo = __float2bfloat16(v - __bfloat162float(hi));
        Thi[(long)n * H + k] = hi;
        Tlo[(long)n * H + k] = lo;
    }
}

// interval bounds of W x + b; warp-per-row, 8 rows per block
__global__ __launch_bounds__(256) void k_affine_interval(
    const float* __restrict__ W, const float* __restrict__ b,
    const float* __restrict__ ub, const float* __restrict__ lb,
    float* __restrict__ uo, float* __restrict__ lo, int cols, int M) {
    int wid = threadIdx.x >> 5, lane = threadIdx.x & 31;
    int row = blockIdx.x * 8 + wid;
    if (row >= M) return;
    const float4* wr = (const float4*)(W + (long)row * cols);
    const float4* u4 = (const float4*)ub;
    const float4* l4 = (const float4*)lb;
    float su = 0.0f, sl = 0.0f;
    int c4 = cols >> 2;
    for (int j = lane; j < c4; j += 32) {
        float4 w = wr[j], u = u4[j], l = l4[j];
        float p, n;
        p = fmaxf(w.x, 0.0f); n = fminf(w.x, 0.0f); su += p * u.x + n * l.x; sl += p * l.x + n * u.x;
        p = fmaxf(w.y, 0.0f); n = fminf(w.y, 0.0f); su += p * u.y + n * l.y; sl += p * l.y + n * u.y;
        p = fmaxf(w.z, 0.0f); n = fminf(w.z, 0.0f); su += p * u.z + n * l.z; sl += p * l.z + n * u.z;
        p = fmaxf(w.w, 0.0f); n = fminf(w.w, 0.0f); su += p * u.w + n * l.w; sl += p * l.w + n * u.w;
    }
    su = warp_reduce(su);
    sl = warp_reduce(sl);
    if (lane == 0) { uo[row] = su + b[row]; lo[row] = sl + b[row]; }
}

// elementwise SPU relaxation analysis (exact reference math)
__global__ void k_spu(const float* __restrict__ ub, const float* __restrict__ lb,
                      float* __restrict__ us, float* __restrict__ ui,
                      float* __restrict__ ls, float* __restrict__ li,
                      float* __restrict__ pub, float* __restrict__ plb) {
    int i = blockIdx.x * blockDim.x + threadIdx.x;
    if (i >= H) return;
    float ux = ub[i], lx = lb[i];
    float uy = spu_(ux), ly = spu_(lx);
    float sj = (uy - ly) / (ux - lx);
    float ij = uy - sj * ux;
    bool right = lx > 0.0f;
    bool left  = ux <= 0.0f;
    float mid = 0.5f * (ux + lx);
    float sp = 2.0f * mid, ip = -mid * mid - 0.5f;
    float sm = sigm_(mid);
    float ssm = -sm * (1.0f - sm), ism = -sm - ssm * mid;
    float nub = fmaxf(uy, ly);
    float nlb, usv, uiv, lsv, liv;
    if (right) {
        usv = sj; uiv = ij; lsv = sp; liv = ip; nlb = fminf(uy, ly);
    } else if (left) {
        usv = ssm; uiv = ism; lsv = sj; liv = ij; nlb = fminf(uy, ly);
    } else {
        nlb = -0.5f;
        float spu2 = 2.0f * ux, ipu = -ux * ux - 0.5f;
        float limit = spu2 * lx + ipu;
        float clm = (fabsf(lx) > ux) ? 1.0f : 0.0f;
        float clp = sigm_((clm - 0.5f) * 10.0f) * (ly - limit) + limit;
        if (clp < -0.5f) {
            float D = 4.0f * lx * lx - 4.0f * clp - 2.0f;
            float x2 = (2.0f * lx + sqrtf(fmaxf(D, 0.0f))) * 0.5f;
            lsv = 2.0f * x2; liv = -x2 * x2 - 0.5f;
        } else {
            lsv = (-0.5f - clp) / (0.0f - lx); liv = -0.5f;
        }
        float sl_ = sigm_(lx);
        float ssl = -sl_ * (1.0f - sl_), isl = -sl_ - ssl * lx;
        float stv = ssl * ux + isl - uy;
        if (stv > 0.0f) {
            float L = lx, R = 0.0f;
#pragma unroll
            for (int t = 0; t < 10; t++) {
                float m = 0.5f * (L + R);
                float s = sigm_(m);
                float sms = -s * (1.0f - s), ims = -s - sms * m;
                bool mask = (sms * ux + ims - uy) > 0.0f;
                L = mask ? m : L;
                R = mask ? R : m;
            }
            float scp = sigm_(-5.0f) * (L - lx) + lx;
            float sc = sigm_(scp);
            usv = -sc * (1.0f - sc);
            uiv = -sc - usv * scp;
        } else {
            usv = sj; uiv = ij;
        }
    }
    us[i] = usv; ui[i] = uiv; ls[i] = lsv; li[i] = liv;
    pub[i] = nub; plb[i] = nlb;
}

// Post-SPU back-substitution collapse (exact identity)
__global__ void k_postspu(const float* __restrict__ sus, const float* __restrict__ sui,
                          const float* __restrict__ sls, const float* __restrict__ sli,
                          const float* __restrict__ rawVu, const float* __restrict__ rawVl,
                          float* __restrict__ pub, float* __restrict__ plb) {
    int i = blockIdx.x * blockDim.x + threadIdx.x;
    if (i >= H) return;
    float su = sus[i], iu = sui[i];
    float vu = (su >= 0.0f) ? rawVu[i] : rawVl[i];
    pub[i] = fminf(pub[i], su * vu + iu);
    float sl = sls[i], il = sli[i];
    float vl = (sl >= 0.0f) ? rawVl[i] : rawVu[i];
    plb[i] = fmaxf(plb[i], sl * vl + il);
}

// Chain-start column-scale from raw layer weights (upper rows [0,Mu), lower [Mu,M));
// emits bf16 hi/lo A operands and initializes the running chain bias.
// Warp-per-row, 8 rows per block.
__global__ __launch_bounds__(256) void k_colscale_start(
    const float* __restrict__ Wsrc, const float* __restrict__ bsrc,
    const float* __restrict__ sus, const float* __restrict__ sui,
    const float* __restrict__ sls, const float* __restrict__ sli,
    const float* __restrict__ blayer,
    __nv_bfloat16* __restrict__ Ahi, __nv_bfloat16* __restrict__ Alo,
    float* __restrict__ Bias, int M, int Mu) {
    int wid = threadIdx.x >> 5, lane = threadIdx.x & 31;
    int row = blockIdx.x * 8 + wid;
    if (row >= M) return;
    bool up = row < Mu;
    int orow = up ? row : row - Mu;
    const float4* ws = (const float4*)(Wsrc + (long)orow * H);
    __nv_bfloat162* ah = (__nv_bfloat162*)(Ahi + (long)row * H);
    __nv_bfloat162* al = (__nv_bfloat162*)(Alo + (long)row * H);
    const float4* ps = (const float4*)(up ? sus : sls);
    const float4* pi = (const float4*)(up ? sui : sli);
    const float4* ns = (const float4*)(up ? sls : sus);
    const float4* ni = (const float4*)(up ? sli : sui);
    const float4* bl = (const float4*)blayer;
    float acc = 0.0f;
#pragma unroll 4
    for (int j = lane; j < H / 4; j += 32) {
        float4 w = ws[j];
        float4 psv = ps[j], piv = pi[j], nsv = ns[j], niv = ni[j], blv = bl[j];
        float4 o;
        float p, n;
        p = fmaxf(w.x, 0.0f); n = fminf(w.x, 0.0f); o.x = p * psv.x + n * nsv.x; acc += p * piv.x + n * niv.x + o.x * blv.x;
        p = fmaxf(w.y, 0.0f); n = fminf(w.y, 0.0f); o.y = p * psv.y + n * nsv.y; acc += p * piv.y + n * niv.y + o.y * blv.y;
        p = fmaxf(w.z, 0.0f); n = fminf(w.z, 0.0f); o.z = p * psv.z + n * nsv.z; acc += p * piv.z + n * niv.z + o.z * blv.z;
        p = fmaxf(w.w, 0.0f); n = fminf(w.w, 0.0f); o.w = p * psv.w + n * nsv.w; acc += p * piv.w + n * niv.w + o.w * blv.w;
        float rx, ry, rz, rw;
        __nv_bfloat162 h01 = split_hi(o.x, o.y, rx, ry);
        __nv_bfloat162 h23 = split_hi(o.z, o.w, rz, rw);
        ah[2 * j]     = h01;
        ah[2 * j + 1] = h23;
        al[2 * j]     = __floats2bfloat162_rn(rx, ry);
        al[2 * j + 1] = __floats2bfloat162_rn(rz, rw);
    }
    acc = warp_reduce(acc);
    if (lane == 0) Bias[row] = bsrc[orow] + acc;
}

// Final interval evaluation at the input layer; warp-per-row.
__global__ __launch_bounds__(256) void k_interval_f(
    const float* __restrict__ W, int ld, const float* __restrict__ bias,
    const float* __restrict__ u0, const float* __restrict__ l0,
    float* __restrict__ ubio, float* __restrict__ lbio,
    float* __restrict__ rawV, int cols, int M, int Mu) {
    int wid = threadIdx.x >> 5, lane = threadIdx.x & 31;
    int row = blockIdx.x * 8 + wid;
    if (row >= M) return;
    bool up = row < Mu;
    int orow = up ? row : row - Mu;
    const float4* wr = (const float4*)(W + (long)row * ld);
    const float4* a4 = (const float4*)(up ? u0 : l0);
    const float4* c4p = (const float4*)(up ? l0 : u0);
    float acc = 0.0f;
    for (int j = lane; j < cols / 4; j += 32) {
        float4 w = wr[j];
        float4 av = a4[j], cv = c4p[j];
        acc += fmaxf(w.x, 0.0f) * av.x + fminf(w.x, 0.0f) * cv.x;
        acc += fmaxf(w.y, 0.0f) * av.y + fminf(w.y, 0.0f) * cv.y;
        acc += fmaxf(w.z, 0.0f) * av.z + fminf(w.z, 0.0f) * cv.z;
        acc += fmaxf(w.w, 0.0f) * av.w + fminf(w.w, 0.0f) * cv.w;
    }
    acc = warp_reduce(acc);
    if (lane == 0) {
        float v = acc + bias[row];
        if (rawV) rawV[row] = v;
        if (up) ubio[orow] = fminf(ubio[orow], v);
        else    lbio[orow] = fmaxf(lbio[orow], v);
    }
}

// ---------------- bf16-split GEMM via mma.sync (HMMA) ----------------
#define GSTRIDE 80
#define TILEB   (128 * GSTRIDE)
#define STAGEB  (4 * TILEB)
#define GEMM_SMEM (2 * STAGEB)

// Shared mainloop: accumulates 128x128 tile of (Ahi+Alo)@(Bhi+Blo)^T (3-term split).
struct GemmCtx {
    float acc[4][4][4];
    int rowBase, colBase, mbase, nbase, lr, lc2;
};

__device__ __forceinline__ void gemm_mainloop(
    GemmCtx& cx, char* dynsm,
    const __nv_bfloat16* __restrict__ Ahi, const __nv_bfloat16* __restrict__ Alo,
    const __nv_bfloat16* __restrict__ Bhi, const __nv_bfloat16* __restrict__ Blo,
    int M) {
    const int tid = threadIdx.x;
    const int wid = tid >> 5;
    const int lane = tid & 31;
    const uint32_t smbase = smem_u32(dynsm);
    const int wm = wid & 1, wn = wid >> 1;
    cx.mbase = wm * 64; cx.nbase = wn * 32;
    cx.lr = lane >> 2; cx.lc2 = 2 * (lane & 3);
#pragma unroll
    for (int mi = 0; mi < 4; mi++)
#pragma unroll
        for (int ni = 0; ni < 4; ni++)
#pragma unroll
            for (int t = 0; t < 4; t++) cx.acc[mi][ni][t] = 0.0f;

    auto issue = [&](int c) {
        const int st = c & 1;
        const uint32_t base = smbase + st * STAGEB;
        const long k0 = (long)c * 32;
#pragma unroll
        for (int p = 0; p < 2; p++) {
            int u = tid + p * 256;
            int row = u >> 2, seg = u & 3;
            uint32_t so = base + row * GSTRIDE + seg * 16;
            long ka = k0 + seg * 8;
            int grow = cx.rowBase + row; if (grow > M - 1) grow = M - 1;
            cp16(so,              Ahi + (long)grow * H + ka);
            cp16(so + TILEB,      Alo + (long)grow * H + ka);
            int gn = cx.colBase + row;
            cp16(so + 2 * TILEB,  Bhi + (long)gn * H + ka);
            cp16(so + 3 * TILEB,  Blo + (long)gn * H + ka);
        }
        asm volatile("cp.async.commit_group;");
    };

    issue(0);
    const int NK = H / 32;
    for (int c = 0; c < NK; ++c) {
        if (c + 1 < NK) {
            issue(c + 1);
            asm volatile("cp.async.wait_group 1;");
        } else {
            asm volatile("cp.async.wait_group 0;");
        }
        __syncthreads();
        const char* sb = dynsm + (c & 1) * STAGEB;
        const char* sA = sb;
        const char* sB = sb + 2 * TILEB;
#pragma unroll
        for (int kk = 0; kk < 32; kk += 16) {
            uint32_t bh[4][2], blo[4][2];
#pragma unroll
            for (int ni = 0; ni < 4; ni++) {
                const char* p = sB + (cx.nbase + ni * 8 + cx.lr) * GSTRIDE + (kk + cx.lc2) * 2;
                bh[ni][0]  = *(const uint32_t*)p;
                bh[ni][1]  = *(const uint32_t*)(p + 16);
                blo[ni][0] = *(const uint32_t*)(p + TILEB);
                blo[ni][1] = *(const uint32_t*)(p + TILEB + 16);
            }
#pragma unroll
            for (int mi = 0; mi < 4; mi++) {
                const char* q = sA + (cx.mbase + mi * 16 + cx.lr) * GSTRIDE + (kk + cx.lc2) * 2;
                uint32_t ah[4], al[4];
                ah[0] = *(const uint32_t*)q;
                ah[1] = *(const uint32_t*)(q + 8 * GSTRIDE);
                ah[2] = *(const uint32_t*)(q + 16);
                ah[3] = *(const uint32_t*)(q + 8 * GSTRIDE + 16);
                al[0] = *(const uint32_t*)(q + TILEB);
                al[1] = *(const uint32_t*)(q + TILEB + 8 * GSTRIDE);
                al[2] = *(const uint32_t*)(q + TILEB + 16);
                al[3] = *(const uint32_t*)(q + TILEB + 8 * GSTRIDE + 16);
#pragma unroll
                for (int ni = 0; ni < 4; ni++) {
                    mma16816(cx.acc[mi][ni], ah, bh[ni]);
                    mma16816(cx.acc[mi][ni], ah, blo[ni]);
                    mma16816(cx.acc[mi][ni], al, bh[ni]);
                }
            }
        }
        __syncthreads();
    }
}

// Plain epilogue: fp32 C (used for the last GEMM of a chain).
__global__ __launch_bounds__(256) void gemm_mma(
    const __nv_bfloat16* __restrict__ Ahi, const __nv_bfloat16* __restrict__ Alo,
    const __nv_bfloat16* __restrict__ Bhi, const __nv_bfloat16* __restrict__ Blo,
    float* __restrict__ C, int M, int ldc) {
    extern __shared__ char dynsm[];
    GemmCtx cx;
    cx.rowBase = blockIdx.y * 128;
    cx.colBase = blockIdx.x * 128;
    gemm_mainloop(cx, dynsm, Ahi, Alo, Bhi, Blo, M);
#pragma unroll
    for (int mi = 0; mi < 4; mi++) {
        int gr0 = cx.rowBase + cx.mbase + mi * 16 + cx.lr;
#pragma unroll
        for (int ni = 0; ni < 4; ni++) {
            int gc = cx.colBase + cx.nbase + ni * 8 + cx.lc2;
            if (gr0 < M) {
                float2 v = make_float2(cx.acc[mi][ni][0], cx.acc[mi][ni][1]);
                *(float2*)(C + (long)gr0 * ldc + gc) = v;
            }
            if (gr0 + 8 < M) {
                float2 v = make_float2(cx.acc[mi][ni][2], cx.acc[mi][ni][3]);
                *(float2*)(C + (long)(gr0 + 8) * ldc + gc) = v;
            }
        }
    }
}

// Fused colscale epilogue: applies the next SPU diagonal pass to the accumulators,
// writes bf16 hi/lo A operands for the next GEMM, and atomically accumulates the
// per-row bias contribution (quad-reduced) into the running chain bias.
__global__ __launch_bounds__(256) void gemm_mma_cs(
    const __nv_bfloat16* __restrict__ Ahi, const __nv_bfloat16* __restrict__ Alo,
    const __nv_bfloat16* __restrict__ Bhi, const __nv_bfloat16* __restrict__ Blo,
    const float* __restrict__ sus, const float* __restrict__ sui,
    const float* __restrict__ sls, const float* __restrict__ sli,
    const float* __restrict__ blayer,
    __nv_bfloat16* __restrict__ Aho, __nv_bfloat16* __restrict__ Alo_o,
    float* __restrict__ Bias, int M, int Mu) {
    extern __shared__ char dynsm[];
    GemmCtx cx;
    cx.rowBase = blockIdx.y * 128;
    cx.colBase = blockIdx.x * 128;
    gemm_mainloop(cx, dynsm, Ahi, Alo, Bhi, Blo, M);

    const bool up = cx.rowBase < Mu;    // Mu is a multiple of 128 (or 0) -> CTA-uniform
    const float* ps = up ? sus : sls;
    const float* pi = up ? sui : sli;
    const float* ns = up ? sls : sus;
    const float* ni_ = up ? sli : sui;
    const int lane = threadIdx.x & 31;

#pragma unroll
    for (int mi = 0; mi < 4; mi++) {
        int gr0 = cx.rowBase + cx.mbase + mi * 16 + cx.lr;
        int gr1 = gr0 + 8;
        float rs0 = 0.0f, rs1 = 0.0f;
#pragma unroll
        for (int ni = 0; ni < 4; ni++) {
            int gc = cx.colBase + cx.nbase + ni * 8 + cx.lc2;
            float s0 = ps[gc], s1 = ps[gc + 1];
            float i0 = pi[gc], i1 = pi[gc + 1];
            float t0 = ns[gc], t1 = ns[gc + 1];
            float u0v = ni_[gc], u1v = ni_[gc + 1];
            float b0 = blayer[gc], b1 = blayer[gc + 1];
            // row gr0: acc[..][0], acc[..][1]
            {
                float v0 = cx.acc[mi][ni][0], v1 = cx.acc[mi][ni][1];
                float p0 = fmaxf(v0, 0.0f), n0 = fminf(v0, 0.0f);
                float p1 = fmaxf(v1, 0.0f), n1 = fminf(v1, 0.0f);
                float o0 = p0 * s0 + n0 * t0;
                float o1 = p1 * s1 + n1 * t1;
                rs0 += p0 * i0 + n0 * u0v + o0 * b0 + p1 * i1 + n1 * u1v + o1 * b1;
                if (gr0 < M) {
                    float rx, ry;
                    __nv_bfloat162 hi2 = split_hi(o0, o1, rx, ry);
                    *(__nv_bfloat162*)(Aho  + (long)gr0 * H + gc) = hi2;
                    *(__nv_bfloat162*)(Alo_o + (long)gr0 * H + gc) = __floats2bfloat162_rn(rx, ry);
                }
            }
            // row gr1: acc[..][2], acc[..][3]
            {
                float v0 = cx.acc[mi][ni][2], v1 = cx.acc[mi][ni][3];
                float p0 = fmaxf(v0, 0.0f), n0 = fminf(v0, 0.0f);
                float p1 = fmaxf(v1, 0.0f), n1 = fminf(v1, 0.0f);
                float o0 = p0 * s0 + n0 * t0;
                float o1 = p1 * s1 + n1 * t1;
                rs1 += p0 * i0 + n0 * u0v + o0 * b0 + p1 * i1 + n1 * u1v + o1 * b1;
                if (gr1 < M) {
                    float rx, ry;
                    __nv_bfloat162 hi2 = split_hi(o0, o1, rx, ry);
                    *(__nv_bfloat162*)(Aho  + (long)gr1 * H + gc) = hi2;
                    *(__nv_bfloat162*)(Alo_o + (long)gr1 * H + gc) = __floats2bfloat162_rn(rx, ry);
                }
            }
        }
        // quad reduce (lanes 4*lr .. 4*lr+3 share the same rows)
        rs0 += __shfl_xor_sync(0xffffffffu, rs0, 1);
        rs0 += __shfl_xor_sync(0xffffffffu, rs0, 2);
        rs1 += __shfl_xor_sync(0xffffffffu, rs1, 1);
        rs1 += __shfl_xor_sync(0xffffffffu, rs1, 2);
        if ((lane & 3) == 0) {
            if (gr0 < M) atomicAdd(Bias + gr0, rs0);
            if (gr1 < M) atomicAdd(Bias + gr1, rs1);
        }
    }
}

__global__ void k_final_min(const float* __restrict__ lb4, float* __restrict__ out) {
    if (threadIdx.x == 0) {
        float m = lb4[0];
#pragma unroll
        for (int i = 1; i < DOUT; i++) m = fminf(m, lb4[i]);
        out[0] = m;
    }
}

// ---------------- host orchestration ----------------
extern "C" void kernel_launch(void* const* d_in, const int* in_sizes, int n_in,
                              void* d_out, int out_size) {
    (void)in_sizes; (void)n_in; (void)out_size;
    const float* inputs = (const float*)d_in[0];
    const float* eps    = (const float*)d_in[1];
    const float* w1 = (const float*)d_in[2]; const float* b1 = (const float*)d_in[3];
    const float* w2 = (const float*)d_in[4]; const float* b2 = (const float*)d_in[5];
    const float* w3 = (const float*)d_in[6]; const float* b3 = (const float*)d_in[7];
    const float* w4 = (const float*)d_in[8]; const float* b4 = (const float*)d_in[9];
    float* out = (float*)d_out;

    cudaFuncSetAttribute(gemm_mma,    cudaFuncAttributeMaxDynamicSharedMemorySize, GEMM_SMEM);
    cudaFuncSetAttribute(gemm_mma_cs, cudaFuncAttributeMaxDynamicSharedMemorySize, GEMM_SMEM);

    float *U0, *L0, *UBL, *LBL, *SUS, *SUI, *SLS, *SLI, *PUB, *PLB, *UB4, *LB4, *RAWV;
    float *W0, *BIAS;
    __nv_bfloat16 *AHI, *ALO, *AH2, *AL2, *T1H, *T1L, *T2H, *T2L, *T3H, *T3L;
    cudaGetSymbolAddress((void**)&U0, g_u0);
    cudaGetSymbolAddress((void**)&L0, g_l0);
    cudaGetSymbolAddress((void**)&UBL, g_ubL);
    cudaGetSymbolAddress((void**)&LBL, g_lbL);
    cudaGetSymbolAddress((void**)&SUS, g_sus);
    cudaGetSymbolAddress((void**)&SUI, g_sui);
    cudaGetSymbolAddress((void**)&SLS, g_sls);
    cudaGetSymbolAddress((void**)&SLI, g_sli);
    cudaGetSymbolAddress((void**)&PUB, g_pub);
    cudaGetSymbolAddress((void**)&PLB, g_plb);
    cudaGetSymbolAddress((void**)&UB4, g_ub4);
    cudaGetSymbolAddress((void**)&LB4, g_lb4);
    cudaGetSymbolAddress((void**)&RAWV, g_rawV);
    cudaGetSymbolAddress((void**)&W0, g_W0);
    cudaGetSymbolAddress((void**)&BIAS, g_Bias);
    cudaGetSymbolAddress((void**)&AHI, g_Ahi);
    cudaGetSymbolAddress((void**)&ALO, g_Alo);
    cudaGetSymbolAddress((void**)&AH2, g_Ahi2);
    cudaGetSymbolAddress((void**)&AL2, g_Alo2);
    cudaGetSymbolAddress((void**)&T1H, g_T1hi);
    cudaGetSymbolAddress((void**)&T1L, g_T1lo);
    cudaGetSymbolAddress((void**)&T2H, g_T2hi);
    cudaGetSymbolAddress((void**)&T2L, g_T2lo);
    cudaGetSymbolAddress((void**)&T3H, g_T3hi);
    cudaGetSymbolAddress((void**)&T3L, g_T3lo);

    const float* LBv[3] = {b1, b2, b3};
    const __nv_bfloat16* TH[3] = {T1H, T2H, T3H};
    const __nv_bfloat16* TL[3] = {T1L, T2L, T3L};

    // transposed + split weights (B operands)
    k_transpose_split<<<dim3(NPAD1 / 32, H / 32), dim3(32, 8)>>>(w1, T1H, T1L, DIN);
    k_transpose_split<<<dim3(H / 32, H / 32),     dim3(32, 8)>>>(w2, T2H, T2L, H);
    k_transpose_split<<<dim3(H / 32, H / 32),     dim3(32, 8)>>>(w3, T3H, T3L, H);

    // Pre-SPU (first back-substitution) descend of W_lvl+1 down to the input box.
    auto descend = [&](const float* sW, const float* sB, int M, int Mu, int lvl,
                       float* ubio, float* lbio, float* rawV) {
        k_colscale_start<<<(M + 7) / 8, 256>>>(sW, sB,
                                               SUS + (lvl - 1) * H, SUI + (lvl - 1) * H,
                                               SLS + (lvl - 1) * H, SLI + (lvl - 1) * H,
                                               LBv[lvl - 1], AHI, ALO, BIAS, M, Mu);
        const __nv_bfloat16 *curH = AHI, *curL = ALO;
        __nv_bfloat16 *nxtH = AH2, *nxtL = AL2;
        for (int l = lvl; l >= 2; --l) {
            dim3 g(H / 128, (M + 127) / 128);
            gemm_mma_cs<<<g, 256, GEMM_SMEM>>>(curH, curL, TH[l - 1], TL[l - 1],
                                               SUS + (l - 2) * H, SUI + (l - 2) * H,
                                               SLS + (l - 2) * H, SLI + (l - 2) * H,
                                               LBv[l - 2], nxtH, nxtL, BIAS, M, Mu);
            const __nv_bfloat16* th = curH; const __nv_bfloat16* tl = curL;
            curH = nxtH; curL = nxtL;
            nxtH = (__nv_bfloat16*)th; nxtL = (__nv_bfloat16*)tl;
        }
        dim3 g(NPAD1 / 128, (M + 127) / 128);
        gemm_mma<<<g, 256, GEMM_SMEM>>>(curH, curL, TH[0], TL[0], W0, M, NPAD1);
        k_interval_f<<<(M + 7) / 8, 256>>>(W0, NPAD1, BIAS, U0, L0, ubio, lbio, rawV,
                                           DIN, M, Mu);
    };

    // input box (normalized)
    k_init_bounds<<<(DIN + 255) / 256, 256>>>(inputs, eps, U0, L0);

    // ---- layer 1 ----
    k_affine_interval<<<H / 8, 256>>>(w1, b1, U0, L0, UBL + 0 * H, LBL + 0 * H, DIN, H);
    k_spu<<<(H + 255) / 256, 256>>>(UBL + 0 * H, LBL + 0 * H,
                                    SUS + 0 * H, SUI + 0 * H, SLS + 0 * H, SLI + 0 * H,
                                    PUB + 0 * H, PLB + 0 * H);
    k_postspu<<<(H + 255) / 256, 256>>>(SUS + 0 * H, SUI + 0 * H, SLS + 0 * H, SLI + 0 * H,
                                        UBL + 0 * H, LBL + 0 * H, PUB + 0 * H, PLB + 0 * H);

    // ---- layer 2 ----
    k_affine_interval<<<H / 8, 256>>>(w2, b2, PUB + 0 * H, PLB + 0 * H,
                                      UBL + 1 * H, LBL + 1 * H, H, H);
    descend(w2, b2, 2 * H, H, 1, UBL + 1 * H, LBL + 1 * H, RAWV);
    k_spu<<<(H + 255) / 256, 256>>>(UBL + 1 * H, LBL + 1 * H,
                                    SUS + 1 * H, SUI + 1 * H, SLS + 1 * H, SLI + 1 * H,
                                    PUB + 1 * H, PLB + 1 * H);
    k_postspu<<<(H + 255) / 256, 256>>>(SUS + 1 * H, SUI + 1 * H, SLS + 1 * H, SLI + 1 * H,
                                        RAWV, RAWV + H, PUB + 1 * H, PLB + 1 * H);

    // ---- layer 3 ----
    k_affine_interval<<<H / 8, 256>>>(w3, b3, PUB + 1 * H, PLB + 1 * H,
                                      UBL + 2 * H, LBL + 2 * H, H, H);
    descend(w3, b3, 2 * H, H, 2, UBL + 2 * H, LBL + 2 * H, RAWV);
    k_spu<<<(H + 255) / 256, 256>>>(UBL + 2 * H, LBL + 2 * H,
                                    SUS + 2 * H, SUI + 2 * H, SLS + 2 * H, SLI + 2 * H,
                                    PUB + 2 * H, PLB + 2 * H);
    k_postspu<<<(H + 255) / 256, 256>>>(SUS + 2 * H, SUI + 2 * H, SLS + 2 * H, SLI + 2 * H,
                                        RAWV, RAWV + H, PUB + 2 * H, PLB + 2 * H);

    // ---- layer 4 (only the lower bound matters for the output) ----
    k_affine_interval<<<(DOUT + 7) / 8, 256>>>(w4, b4, PUB + 2 * H, PLB + 2 * H,
                                               UB4, LB4, H, DOUT);
    descend(w4, b4, DOUT, 0, 3, nullptr, LB4, nullptr);

    k_final_min<<<1, 32>>>(LB4, out);
}

// round 9
// speedup vs baseline: 1.0400x; 1.0400x over previous
#include <cuda_runtime.h>
#include <cuda_bf16.h>
#include <cstdint>
#include <math.h>

#define H    2048
#define DIN  784
#define DOUT 10
#define NPAD1 896                 // DIN padded to a multiple of 128

// ---------------- scratch (device globals; no allocations allowed) ----------------
__device__ __align__(256) float g_u0[DIN], g_l0[DIN];
__device__ __align__(256) float g_ubL[3 * H], g_lbL[3 * H];
__device__ __align__(256) float g_sus[3 * H], g_sui[3 * H];
__device__ __align__(256) float g_sls[3 * H], g_sli[3 * H];
__device__ __align__(256) float g_pub[3 * H], g_plb[3 * H];
__device__ __align__(256) float g_ub4[DOUT], g_lb4[DOUT];
__device__ __align__(256) float g_rawV[2 * H];                // raw descended values (u | l)
__device__ __align__(256) float g_W0[(long)2 * H * NPAD1];    // final-GEMM fp32 output
__device__ __align__(256) float g_Bias[2 * H];                // running chain bias
// bf16 split operand buffers (ping-pong A) + transposed weights (B)
__device__ __align__(256) __nv_bfloat16 g_Ahi[(long)2 * H * H];
__device__ __align__(256) __nv_bfloat16 g_Alo[(long)2 * H * H];
__device__ __align__(256) __nv_bfloat16 g_Ahi2[(long)2 * H * H];
__device__ __align__(256) __nv_bfloat16 g_Alo2[(long)2 * H * H];
__device__ __align__(256) __nv_bfloat16 g_T1hi[(long)NPAD1 * H], g_T1lo[(long)NPAD1 * H];
__device__ __align__(256) __nv_bfloat16 g_T2hi[(long)H * H],     g_T2lo[(long)H * H];
__device__ __align__(256) __nv_bfloat16 g_T3hi[(long)H * H],     g_T3lo[(long)H * H];

// ---------------- small device helpers ----------------
__device__ __forceinline__ float sigm_(float x) { return 1.0f / (1.0f + expf(-x)); }
__device__ __forceinline__ float spu_(float x) {
    return (x >= 0.0f) ? (x * x - 0.5f) : (sigm_(-x) - 1.0f);
}
__device__ __forceinline__ float warp_reduce(float v) {
#pragma unroll
    for (int o = 16; o > 0; o >>= 1) v += __shfl_down_sync(0xffffffffu, v, o);
    return v;
}
__device__ __forceinline__ uint32_t smem_u32(const void* p) {
    uint32_t a;
    asm("{ .reg .u64 t; cvta.to.shared.u64 t, %1; cvt.u32.u64 %0, t; }" : "=r"(a) : "l"(p));
    return a;
}
__device__ __forceinline__ void cp16(uint32_t dst, const void* src) {
    asm volatile("cp.async.cg.shared.global [%0], [%1], 16;" :: "r"(dst), "l"(src));
}
__device__ __forceinline__ void mma16816(float* d, const uint32_t* a, const uint32_t* b) {
    asm volatile(
        "mma.sync.aligned.m16n8k16.row.col.f32.bf16.bf16.f32 "
        "{%0,%1,%2,%3}, {%4,%5,%6,%7}, {%8,%9}, {%0,%1,%2,%3};"
        : "+f"(d[0]), "+f"(d[1]), "+f"(d[2]), "+f"(d[3])
        : "r"(a[0]), "r"(a[1]), "r"(a[2]), "r"(a[3]), "r"(b[0]), "r"(b[1]));
}
__device__ __forceinline__ void ldsm_x4(uint32_t a, uint32_t* r) {
    asm volatile("ldmatrix.sync.aligned.m8n8.x4.shared.b16 {%0,%1,%2,%3}, [%4];"
                 : "=r"(r[0]), "=r"(r[1]), "=r"(r[2]), "=r"(r[3]) : "r"(a));
}
__device__ __forceinline__ void ldsm_x2(uint32_t a, uint32_t* r) {
    asm volatile("ldmatrix.sync.aligned.m8n8.x2.shared.b16 {%0,%1}, [%2];"
                 : "=r"(r[0]), "=r"(r[1]) : "r"(a));
}
__device__ __forceinline__ __nv_bfloat162 split_hi(float a, float b, float& ra, float& rb) {
    __nv_bfloat16 ha = __float2bfloat16(a), hb = __float2bfloat16(b);
    ra = a - __bfloat162float(ha);
    rb = b - __bfloat162float(hb);
    return __halves2bfloat162(ha, hb);
}

// ---------------- elementwise kernels ----------------
__global__ void k_init_bounds(const float* __restrict__ in, const float* __restrict__ epsp,
                              float* __restrict__ u0, float* __restrict__ l0) {
    int i = blockIdx.x * blockDim.x + threadIdx.x;
    if (i >= DIN) return;
    float e = epsp[0];
    float u = fminf(in[i] + e, 1.0f);
    float l = fmaxf(in[i] - e, 0.0f);
    u0[i] = (u - 0.1307f) / 0.3081f;
    l0[i] = (l - 0.1307f) / 0.3081f;
}

// transpose + bf16 split: T[n][k] = W[k][n]; rows n >= N (padding) are zero.
__global__ void k_transpose_split(const float* __restrict__ W,
                                  __nv_bfloat16* __restrict__ Thi,
                                  __nv_bfloat16* __restrict__ Tlo, int N) {
    __shared__ float t[32][33];
    int n0 = blockIdx.x * 32, k0 = blockIdx.y * 32;
    int tx = threadIdx.x, ty = threadIdx.y;
#pragma unroll
    for (int i = 0; i < 4; i++) {
        int k = k0 + ty + 8 * i;
        int n = n0 + tx;
        t[ty + 8 * i][tx] = (n < N) ? W[(long)k * N + n] : 0.0f;
    }
    __syncthreads();
#pragma unroll
    for (int i = 0; i < 4; i++) {
        int n = n0 + ty + 8 * i;
        int k = k0 + tx;
        float v = t[tx][ty + 8 * i];
        __nv_bfloat16 hi = __float2bfloat16(v);
        __nv_bfloat16 lo = __float2bfloat16(v - __bfloat162float(hi));
        Thi[(long)n * H + k] = hi;
        Tlo[(long)n * H + k] = lo;
    }
}

// interval bounds of W x + b; warp-per-row, 8 rows per block
__global__ __launch_bounds__(256) void k_affine_interval(
    const float* __restrict__ W, const float* __restrict__ b,
    const float* __restrict__ ub, const float* __restrict__ lb,
    float* __restrict__ uo, float* __restrict__ lo, int cols, int M) {
    int wid = threadIdx.x >> 5, lane = threadIdx.x & 31;
    int row = blockIdx.x * 8 + wid;
    if (row >= M) return;
    const float4* wr = (const float4*)(W + (long)row * cols);
    const float4* u4 = (const float4*)ub;
    const float4* l4 = (const float4*)lb;
    float su = 0.0f, sl = 0.0f;
    int c4 = cols >> 2;
    for (int j = lane; j < c4; j += 32) {
        float4 w = wr[j], u = u4[j], l = l4[j];
        float p, n;
        p = fmaxf(w.x, 0.0f); n = fminf(w.x, 0.0f); su += p * u.x + n * l.x; sl += p * l.x + n * u.x;
        p = fmaxf(w.y, 0.0f); n = fminf(w.y, 0.0f); su += p * u.y + n * l.y; sl += p * l.y + n * u.y;
        p = fmaxf(w.z, 0.0f); n = fminf(w.z, 0.0f); su += p * u.z + n * l.z; sl += p * l.z + n * u.z;
        p = fmaxf(w.w, 0.0f); n = fminf(w.w, 0.0f); su += p * u.w + n * l.w; sl += p * l.w + n * u.w;
    }
    su = warp_reduce(su);
    sl = warp_reduce(sl);
    if (lane == 0) { uo[row] = su + b[row]; lo[row] = sl + b[row]; }
}

// elementwise SPU relaxation analysis (exact reference math)
__global__ void k_spu(const float* __restrict__ ub, const float* __restrict__ lb,
                      float* __restrict__ us, float* __restrict__ ui,
                      float* __restrict__ ls, float* __restrict__ li,
                      float* __restrict__ pub, float* __restrict__ plb) {
    int i = blockIdx.x * blockDim.x + threadIdx.x;
    if (i >= H) return;
    float ux = ub[i], lx = lb[i];
    float uy = spu_(ux), ly = spu_(lx);
    float sj = (uy - ly) / (ux - lx);
    float ij = uy - sj * ux;
    bool right = lx > 0.0f;
    bool left  = ux <= 0.0f;
    float mid = 0.5f * (ux + lx);
    float sp = 2.0f * mid, ip = -mid * mid - 0.5f;
    float sm = sigm_(mid);
    float ssm = -sm * (1.0f - sm), ism = -sm - ssm * mid;
    float nub = fmaxf(uy, ly);
    float nlb, usv, uiv, lsv, liv;
    if (right) {
        usv = sj; uiv = ij; lsv = sp; liv = ip; nlb = fminf(uy, ly);
    } else if (left) {
        usv = ssm; uiv = ism; lsv = sj; liv = ij; nlb = fminf(uy, ly);
    } else {
        nlb = -0.5f;
        float spu2 = 2.0f * ux, ipu = -ux * ux - 0.5f;
        float limit = spu2 * lx + ipu;
        float clm = (fabsf(lx) > ux) ? 1.0f : 0.0f;
        float clp = sigm_((clm - 0.5f) * 10.0f) * (ly - limit) + limit;
        if (clp < -0.5f) {
            float D = 4.0f * lx * lx - 4.0f * clp - 2.0f;
            float x2 = (2.0f * lx + sqrtf(fmaxf(D, 0.0f))) * 0.5f;
            lsv = 2.0f * x2; liv = -x2 * x2 - 0.5f;
        } else {
            lsv = (-0.5f - clp) / (0.0f - lx); liv = -0.5f;
        }
        float sl_ = sigm_(lx);
        float ssl = -sl_ * (1.0f - sl_), isl = -sl_ - ssl * lx;
        float stv = ssl * ux + isl - uy;
        if (stv > 0.0f) {
            float L = lx, R = 0.0f;
#pragma unroll
            for (int t = 0; t < 10; t++) {
                float m = 0.5f * (L + R);
                float s = sigm_(m);
                float sms = -s * (1.0f - s), ims = -s - sms * m;
                bool mask = (sms * ux + ims - uy) > 0.0f;
                L = mask ? m : L;
                R = mask ? R : m;
            }
            float scp = sigm_(-5.0f) * (L - lx) + lx;
            float sc = sigm_(scp);
            usv = -sc * (1.0f - sc);
            uiv = -sc - usv * scp;
        } else {
            usv = sj; uiv = ij;
        }
    }
    us[i] = usv; ui[i] = uiv; ls[i] = lsv; li[i] = liv;
    pub[i] = nub; plb[i] = nlb;
}

// Post-SPU back-substitution collapse (exact identity)
__global__ void k_postspu(const float* __restrict__ sus, const float* __restrict__ sui,
                          const float* __restrict__ sls, const float* __restrict__ sli,
                          const float* __restrict__ rawVu, const float* __restrict__ rawVl,
                          float* __restrict__ pub, float* __restrict__ plb) {
    int i = blockIdx.x * blockDim.x + threadIdx.x;
    if (i >= H) return;
    float su = sus[i], iu = sui[i];
    float vu = (su >= 0.0f) ? rawVu[i] : rawVl[i];
    pub[i] = fminf(pub[i], su * vu + iu);
    float sl = sls[i], il = sli[i];
    float vl = (sl >= 0.0f) ? rawVl[i] : rawVu[i];
    plb[i] = fmaxf(plb[i], sl * vl + il);
}

// Chain-start column-scale from raw layer weights (upper rows [0,Mu), lower [Mu,M));
// emits bf16 hi/lo A operands and initializes the running chain bias.
__global__ __launch_bounds__(256) void k_colscale_start(
    const float* __restrict__ Wsrc, const float* __restrict__ bsrc,
    const float* __restrict__ sus, const float* __restrict__ sui,
    const float* __restrict__ sls, const float* __restrict__ sli,
    const float* __restrict__ blayer,
    __nv_bfloat16* __restrict__ Ahi, __nv_bfloat16* __restrict__ Alo,
    float* __restrict__ Bias, int M, int Mu) {
    int wid = threadIdx.x >> 5, lane = threadIdx.x & 31;
    int row = blockIdx.x * 8 + wid;
    if (row >= M) return;
    bool up = row < Mu;
    int orow = up ? row : row - Mu;
    const float4* ws = (const float4*)(Wsrc + (long)orow * H);
    __nv_bfloat162* ah = (__nv_bfloat162*)(Ahi + (long)row * H);
    __nv_bfloat162* al = (__nv_bfloat162*)(Alo + (long)row * H);
    const float4* ps = (const float4*)(up ? sus : sls);
    const float4* pi = (const float4*)(up ? sui : sli);
    const float4* ns = (const float4*)(up ? sls : sus);
    const float4* ni = (const float4*)(up ? sli : sui);
    const float4* bl = (const float4*)blayer;
    float acc = 0.0f;
#pragma unroll 4
    for (int j = lane; j < H / 4; j += 32) {
        float4 w = ws[j];
        float4 psv = ps[j], piv = pi[j], nsv = ns[j], niv = ni[j], blv = bl[j];
        float4 o;
        float p, n;
        p = fmaxf(w.x, 0.0f); n = fminf(w.x, 0.0f); o.x = p * psv.x + n * nsv.x; acc += p * piv.x + n * niv.x + o.x * blv.x;
        p = fmaxf(w.y, 0.0f); n = fminf(w.y, 0.0f); o.y = p * psv.y + n * nsv.y; acc += p * piv.y + n * niv.y + o.y * blv.y;
        p = fmaxf(w.z, 0.0f); n = fminf(w.z, 0.0f); o.z = p * psv.z + n * nsv.z; acc += p * piv.z + n * niv.z + o.z * blv.z;
        p = fmaxf(w.w, 0.0f); n = fminf(w.w, 0.0f); o.w = p * psv.w + n * nsv.w; acc += p * piv.w + n * niv.w + o.w * blv.w;
        float rx, ry, rz, rw;
        __nv_bfloat162 h01 = split_hi(o.x, o.y, rx, ry);
        __nv_bfloat162 h23 = split_hi(o.z, o.w, rz, rw);
        ah[2 * j]     = h01;
        ah[2 * j + 1] = h23;
        al[2 * j]     = __floats2bfloat162_rn(rx, ry);
        al[2 * j + 1] = __floats2bfloat162_rn(rz, rw);
    }
    acc = warp_reduce(acc);
    if (lane == 0) Bias[row] = bsrc[orow] + acc;
}

// Final interval evaluation at the input layer; warp-per-row.
__global__ __launch_bounds__(256) void k_interval_f(
    const float* __restrict__ W, int ld, const float* __restrict__ bias,
    const float* __restrict__ u0, const float* __restrict__ l0,
    float* __restrict__ ubio, float* __restrict__ lbio,
    float* __restrict__ rawV, int cols, int M, int Mu) {
    int wid = threadIdx.x >> 5, lane = threadIdx.x & 31;
    int row = blockIdx.x * 8 + wid;
    if (row >= M) return;
    bool up = row < Mu;
    int orow = up ? row : row - Mu;
    const float4* wr = (const float4*)(W + (long)row * ld);
    const float4* a4 = (const float4*)(up ? u0 : l0);
    const float4* c4p = (const float4*)(up ? l0 : u0);
    float acc = 0.0f;
    for (int j = lane; j < cols / 4; j += 32) {
        float4 w = wr[j];
        float4 av = a4[j], cv = c4p[j];
        acc += fmaxf(w.x, 0.0f) * av.x + fminf(w.x, 0.0f) * cv.x;
        acc += fmaxf(w.y, 0.0f) * av.y + fminf(w.y, 0.0f) * cv.y;
        acc += fmaxf(w.z, 0.0f) * av.z + fminf(w.z, 0.0f) * cv.z;
        acc += fmaxf(w.w, 0.0f) * av.w + fminf(w.w, 0.0f) * cv.w;
    }
    acc = warp_reduce(acc);
    if (lane == 0) {
        float v = acc + bias[row];
        if (rawV) rawV[row] = v;
        if (up) ubio[orow] = fminf(ubio[orow], v);
        else    lbio[orow] = fmaxf(lbio[orow], v);
    }
}

// ---------------- bf16-split GEMM via mma.sync (HMMA) ----------------
#define GSTRIDE 80
#define TILEB   (128 * GSTRIDE)
#define STAGEB  (4 * TILEB)
#define GEMM_SMEM (2 * STAGEB)

// Shared mainloop: accumulates 128x128 tile of (Ahi+Alo)@(Bhi+Blo)^T (3-term split).
struct GemmCtx {
    float acc[4][4][4];
    int rowBase, colBase, mbase, nbase, lr, lc2;
};

__device__ __forceinline__ void gemm_mainloop(
    GemmCtx& cx, char* dynsm,
    const __nv_bfloat16* __restrict__ Ahi, const __nv_bfloat16* __restrict__ Alo,
    const __nv_bfloat16* __restrict__ Bhi, const __nv_bfloat16* __restrict__ Blo,
    int M) {
    const int tid = threadIdx.x;
    const int wid = tid >> 5;
    const int lane = tid & 31;
    const uint32_t smbase = smem_u32(dynsm);
    const int wm = wid & 1, wn = wid >> 1;
    cx.mbase = wm * 64; cx.nbase = wn * 32;
    cx.lr = lane >> 2; cx.lc2 = 2 * (lane & 3);
#pragma unroll
    for (int mi = 0; mi < 4; mi++)
#pragma unroll
        for (int ni = 0; ni < 4; ni++)
#pragma unroll
            for (int t = 0; t < 4; t++) cx.acc[mi][ni][t] = 0.0f;

    // ldmatrix lane addressing (byte offsets within a tile)
    const uint32_t aRowOff = (uint32_t)(cx.mbase + (lane & 15)) * GSTRIDE + (lane >> 4) * 16;
    const uint32_t bRowOff = (uint32_t)(cx.nbase + (lane & 7)) * GSTRIDE + ((lane >> 3) & 1) * 16;

    auto issue = [&](int c) {
        const int st = c & 1;
        const uint32_t base = smbase + st * STAGEB;
        const long k0 = (long)c * 32;
#pragma unroll
        for (int p = 0; p < 2; p++) {
            int u = tid + p * 256;
            int row = u >> 2, seg = u & 3;
            uint32_t so = base + row * GSTRIDE + seg * 16;
            long ka = k0 + seg * 8;
            int grow = cx.rowBase + row; if (grow > M - 1) grow = M - 1;
            cp16(so,              Ahi + (long)grow * H + ka);
            cp16(so + TILEB,      Alo + (long)grow * H + ka);
            int gn = cx.colBase + row;
            cp16(so + 2 * TILEB,  Bhi + (long)gn * H + ka);
            cp16(so + 3 * TILEB,  Blo + (long)gn * H + ka);
        }
        asm volatile("cp.async.commit_group;");
    };

    issue(0);
    const int NK = H / 32;
    for (int c = 0; c < NK; ++c) {
        if (c + 1 < NK) {
            issue(c + 1);
            asm volatile("cp.async.wait_group 1;");
        } else {
            asm volatile("cp.async.wait_group 0;");
        }
        __syncthreads();
        const uint32_t sbu = smbase + (c & 1) * STAGEB;
        const uint32_t sAu = sbu + aRowOff;              // A-tile lane base
        const uint32_t sBu = sbu + 2 * TILEB + bRowOff;  // B-tile lane base
#pragma unroll
        for (int kk = 0; kk < 32; kk += 16) {
            const uint32_t kb = (uint32_t)(kk * 2);
            uint32_t bh[4][2], blo[4][2];
#pragma unroll
            for (int ni = 0; ni < 4; ni++) {
                uint32_t pb = sBu + (uint32_t)(ni * 8) * GSTRIDE + kb;
                ldsm_x2(pb, bh[ni]);
                ldsm_x2(pb + TILEB, blo[ni]);
            }
#pragma unroll
            for (int mi = 0; mi < 4; mi++) {
                uint32_t pa = sAu + (uint32_t)(mi * 16) * GSTRIDE + kb;
                uint32_t ah[4], al[4];
                ldsm_x4(pa, ah);
                ldsm_x4(pa + TILEB, al);
#pragma unroll
                for (int ni = 0; ni < 4; ni++) {
                    mma16816(cx.acc[mi][ni], ah, bh[ni]);
                    mma16816(cx.acc[mi][ni], ah, blo[ni]);
                    mma16816(cx.acc[mi][ni], al, bh[ni]);
                }
            }
        }
        __syncthreads();
    }
}

// Plain epilogue: fp32 C (used for the last GEMM of a chain).
__global__ __launch_bounds__(256) void gemm_mma(
    const __nv_bfloat16* __restrict__ Ahi, const __nv_bfloat16* __restrict__ Alo,
    const __nv_bfloat16* __restrict__ Bhi, const __nv_bfloat16* __restrict__ Blo,
    float* __restrict__ C, int M, int ldc) {
    extern __shared__ char dynsm[];
    GemmCtx cx;
    cx.rowBase = blockIdx.y * 128;
    cx.colBase = blockIdx.x * 128;
    gemm_mainloop(cx, dynsm, Ahi, Alo, Bhi, Blo, M);
#pragma unroll
    for (int mi = 0; mi < 4; mi++) {
        int gr0 = cx.rowBase + cx.mbase + mi * 16 + cx.lr;
#pragma unroll
        for (int ni = 0; ni < 4; ni++) {
            int gc = cx.colBase + cx.nbase + ni * 8 + cx.lc2;
            if (gr0 < M) {
                float2 v = make_float2(cx.acc[mi][ni][0], cx.acc[mi][ni][1]);
                *(float2*)(C + (long)gr0 * ldc + gc) = v;
            }
            if (gr0 + 8 < M) {
                float2 v = make_float2(cx.acc[mi][ni][2], cx.acc[mi][ni][3]);
                *(float2*)(C + (long)(gr0 + 8) * ldc + gc) = v;
            }
        }
    }
}

// Fused colscale epilogue: applies the next SPU diagonal pass to the accumulators,
// writes bf16 hi/lo A operands for the next GEMM, and atomically accumulates the
// per-row bias contribution (quad-reduced) into the running chain bias.
__global__ __launch_bounds__(256) void gemm_mma_cs(
    const __nv_bfloat16* __restrict__ Ahi, const __nv_bfloat16* __restrict__ Alo,
    const __nv_bfloat16* __restrict__ Bhi, const __nv_bfloat16* __restrict__ Blo,
    const float* __restrict__ sus, const float* __restrict__ sui,
    const float* __restrict__ sls, const float* __restrict__ sli,
    const float* __restrict__ blayer,
    __nv_bfloat16* __restrict__ Aho, __nv_bfloat16* __restrict__ Alo_o,
    float* __restrict__ Bias, int M, int Mu) {
    extern __shared__ char dynsm[];
    GemmCtx cx;
    cx.rowBase = blockIdx.y * 128;
    cx.colBase = blockIdx.x * 128;
    gemm_mainloop(cx, dynsm, Ahi, Alo, Bhi, Blo, M);

    const bool up = cx.rowBase < Mu;    // Mu is a multiple of 128 (or 0) -> CTA-uniform
    const float* ps = up ? sus : sls;
    const float* pi = up ? sui : sli;
    const float* ns = up ? sls : sus;
    const float* ni_ = up ? sli : sui;
    const int lane = threadIdx.x & 31;

#pragma unroll
    for (int mi = 0; mi < 4; mi++) {
        int gr0 = cx.rowBase + cx.mbase + mi * 16 + cx.lr;
        int gr1 = gr0 + 8;
        float rs0 = 0.0f, rs1 = 0.0f;
#pragma unroll
        for (int ni = 0; ni < 4; ni++) {
            int gc = cx.colBase + cx.nbase + ni * 8 + cx.lc2;
            float s0 = ps[gc], s1 = ps[gc + 1];
            float i0 = pi[gc], i1 = pi[gc + 1];
            float t0 = ns[gc], t1 = ns[gc + 1];
            float u0v = ni_[gc], u1v = ni_[gc + 1];
            float b0 = blayer[gc], b1 = blayer[gc + 1];
            {
                float v0 = cx.acc[mi][ni][0], v1 = cx.acc[mi][ni][1];
                float p0 = fmaxf(v0, 0.0f), n0 = fminf(v0, 0.0f);
                float p1 = fmaxf(v1, 0.0f), n1 = fminf(v1, 0.0f);
                float o0 = p0 * s0 + n0 * t0;
                float o1 = p1 * s1 + n1 * t1;
                rs0 += p0 * i0 + n0 * u0v + o0 * b0 + p1 * i1 + n1 * u1v + o1 * b1;
                if (gr0 < M) {
                    float rx, ry;
                    __nv_bfloat162 hi2 = split_hi(o0, o1, rx, ry);
                    *(__nv_bfloat162*)(Aho  + (long)gr0 * H + gc) = hi2;
                    *(__nv_bfloat162*)(Alo_o + (long)gr0 * H + gc) = __floats2bfloat162_rn(rx, ry);
                }
            }
            {
                float v0 = cx.acc[mi][ni][2], v1 = cx.acc[mi][ni][3];
                float p0 = fmaxf(v0, 0.0f), n0 = fminf(v0, 0.0f);
                float p1 = fmaxf(v1, 0.0f), n1 = fminf(v1, 0.0f);
                float o0 = p0 * s0 + n0 * t0;
                float o1 = p1 * s1 + n1 * t1;
                rs1 += p0 * i0 + n0 * u0v + o0 * b0 + p1 * i1 + n1 * u1v + o1 * b1;
                if (gr1 < M) {
                    float rx, ry;
                    __nv_bfloat162 hi2 = split_hi(o0, o1, rx, ry);
                    *(__nv_bfloat162*)(Aho  + (long)gr1 * H + gc) = hi2;
                    *(__nv_bfloat162*)(Alo_o + (long)gr1 * H + gc) = __floats2bfloat162_rn(rx, ry);
                }
            }
        }
        rs0 += __shfl_xor_sync(0xffffffffu, rs0, 1);
        rs0 += __shfl_xor_sync(0xffffffffu, rs0, 2);
        rs1 += __shfl_xor_sync(0xffffffffu, rs1, 1);
        rs1 += __shfl_xor_sync(0xffffffffu, rs1, 2);
        if ((lane & 3) == 0) {
            if (gr0 < M) atomicAdd(Bias + gr0, rs0);
            if (gr1 < M) atomicAdd(Bias + gr1, rs1);
        }
    }
}

__global__ void k_final_min(const float* __restrict__ lb4, float* __restrict__ out) {
    if (threadIdx.x == 0) {
        float m = lb4[0];
#pragma unroll
        for (int i = 1; i < DOUT; i++) m = fminf(m, lb4[i]);
        out[0] = m;
    }
}

// ---------------- host orchestration ----------------
extern "C" void kernel_launch(void* const* d_in, const int* in_sizes, int n_in,
                              void* d_out, int out_size) {
    (void)in_sizes; (void)n_in; (void)out_size;
    const float* inputs = (const float*)d_in[0];
    const float* eps    = (const float*)d_in[1];
    const float* w1 = (const float*)d_in[2]; const float* b1 = (const float*)d_in[3];
    const float* w2 = (const float*)d_in[4]; const float* b2 = (const float*)d_in[5];
    const float* w3 = (const float*)d_in[6]; const float* b3 = (const float*)d_in[7];
    const float* w4 = (const float*)d_in[8]; const float* b4 = (const float*)d_in[9];
    float* out = (float*)d_out;

    cudaFuncSetAttribute(gemm_mma,    cudaFuncAttributeMaxDynamicSharedMemorySize, GEMM_SMEM);
    cudaFuncSetAttribute(gemm_mma_cs, cudaFuncAttributeMaxDynamicSharedMemorySize, GEMM_SMEM);

    float *U0, *L0, *UBL, *LBL, *SUS, *SUI, *SLS, *SLI, *PUB, *PLB, *UB4, *LB4, *RAWV;
    float *W0, *BIAS;
    __nv_bfloat16 *AHI, *ALO, *AH2, *AL2, *T1H, *T1L, *T2H, *T2L, *T3H, *T3L;
    cudaGetSymbolAddress((void**)&U0, g_u0);
    cudaGetSymbolAddress((void**)&L0, g_l0);
    cudaGetSymbolAddress((void**)&UBL, g_ubL);
    cudaGetSymbolAddress((void**)&LBL, g_lbL);
    cudaGetSymbolAddress((void**)&SUS, g_sus);
    cudaGetSymbolAddress((void**)&SUI, g_sui);
    cudaGetSymbolAddress((void**)&SLS, g_sls);
    cudaGetSymbolAddress((void**)&SLI, g_sli);
    cudaGetSymbolAddress((void**)&PUB, g_pub);
    cudaGetSymbolAddress((void**)&PLB, g_plb);
    cudaGetSymbolAddress((void**)&UB4, g_ub4);
    cudaGetSymbolAddress((void**)&LB4, g_lb4);
    cudaGetSymbolAddress((void**)&RAWV, g_rawV);
    cudaGetSymbolAddress((void**)&W0, g_W0);
    cudaGetSymbolAddress((void**)&BIAS, g_Bias);
    cudaGetSymbolAddress((void**)&AHI, g_Ahi);
    cudaGetSymbolAddress((void**)&ALO, g_Alo);
    cudaGetSymbolAddress((void**)&AH2, g_Ahi2);
    cudaGetSymbolAddress((void**)&AL2, g_Alo2);
    cudaGetSymbolAddress((void**)&T1H, g_T1hi);
    cudaGetSymbolAddress((void**)&T1L, g_T1lo);
    cudaGetSymbolAddress((void**)&T2H, g_T2hi);
    cudaGetSymbolAddress((void**)&T2L, g_T2lo);
    cudaGetSymbolAddress((void**)&T3H, g_T3hi);
    cudaGetSymbolAddress((void**)&T3L, g_T3lo);

    const float* LBv[3] = {b1, b2, b3};
    const __nv_bfloat16* TH[3] = {T1H, T2H, T3H};
    const __nv_bfloat16* TL[3] = {T1L, T2L, T3L};

    // transposed + split weights (B operands)
    k_transpose_split<<<dim3(NPAD1 / 32, H / 32), dim3(32, 8)>>>(w1, T1H, T1L, DIN);
    k_transpose_split<<<dim3(H / 32, H / 32),     dim3(32, 8)>>>(w2, T2H, T2L, H);
    k_transpose_split<<<dim3(H / 32, H / 32),     dim3(32, 8)>>>(w3, T3H, T3L, H);

    // Pre-SPU (first back-substitution) descend of W_lvl+1 down to the input box.
    auto descend = [&](const float* sW, const float* sB, int M, int Mu, int lvl,
                       float* ubio, float* lbio, float* rawV) {
        k_colscale_start<<<(M + 7) / 8, 256>>>(sW, sB,
                                               SUS + (lvl - 1) * H, SUI + (lvl - 1) * H,
                                               SLS + (lvl - 1) * H, SLI + (lvl - 1) * H,
                                               LBv[lvl - 1], AHI, ALO, BIAS, M, Mu);
        const __nv_bfloat16 *curH = AHI, *curL = ALO;
        __nv_bfloat16 *nxtH = AH2, *nxtL = AL2;
        for (int l = lvl; l >= 2; --l) {
            dim3 g(H / 128, (M + 127) / 128);
            gemm_mma_cs<<<g, 256, GEMM_SMEM>>>(curH, curL, TH[l - 1], TL[l - 1],
                                               SUS + (l - 2) * H, SUI + (l - 2) * H,
                                               SLS + (l - 2) * H, SLI + (l - 2) * H,
                                               LBv[l - 2], nxtH, nxtL, BIAS, M, Mu);
            const __nv_bfloat16* th = curH; const __nv_bfloat16* tl = curL;
            curH = nxtH; curL = nxtL;
            nxtH = (__nv_bfloat16*)th; nxtL = (__nv_bfloat16*)tl;
        }
        dim3 g(NPAD1 / 128, (M + 127) / 128);
        gemm_mma<<<g, 256, GEMM_SMEM>>>(curH, curL, TH[0], TL[0], W0, M, NPAD1);
        k_interval_f<<<(M + 7) / 8, 256>>>(W0, NPAD1, BIAS, U0, L0, ubio, lbio, rawV,
                                           DIN, M, Mu);
    };

    // input box (normalized)
    k_init_bounds<<<(DIN + 255) / 256, 256>>>(inputs, eps, U0, L0);

    // ---- layer 1 ----
    k_affine_interval<<<H / 8, 256>>>(w1, b1, U0, L0, UBL + 0 * H, LBL + 0 * H, DIN, H);
    k_spu<<<(H + 255) / 256, 256>>>(UBL + 0 * H, LBL + 0 * H,
                                    SUS + 0 * H, SUI + 0 * H, SLS + 0 * H, SLI + 0 * H,
                                    PUB + 0 * H, PLB + 0 * H);
    k_postspu<<<(H + 255) / 256, 256>>>(SUS + 0 * H, SUI + 0 * H, SLS + 0 * H, SLI + 0 * H,
                                        UBL + 0 * H, LBL + 0 * H, PUB + 0 * H, PLB + 0 * H);

    // ---- layer 2 ----
    k_affine_interval<<<H / 8, 256>>>(w2, b2, PUB + 0 * H, PLB + 0 * H,
                                      UBL + 1 * H, LBL + 1 * H, H, H);
    descend(w2, b2, 2 * H, H, 1, UBL + 1 * H, LBL + 1 * H, RAWV);
    k_spu<<<(H + 255) / 256, 256>>>(UBL + 1 * H, LBL + 1 * H,
                                    SUS + 1 * H, SUI + 1 * H, SLS + 1 * H, SLI + 1 * H,
                                    PUB + 1 * H, PLB + 1 * H);
    k_postspu<<<(H + 255) / 256, 256>>>(SUS + 1 * H, SUI + 1 * H, SLS + 1 * H, SLI + 1 * H,
                                        RAWV, RAWV + H, PUB + 1 * H, PLB + 1 * H);

    // ---- layer 3 ----
    k_affine_interval<<<H / 8, 256>>>(w3, b3, PUB + 1 * H, PLB + 1 * H,
                                      UBL + 2 * H, LBL + 2 * H, H, H);
    descend(w3, b3, 2 * H, H, 2, UBL + 2 * H, LBL + 2 * H, RAWV);
    k_spu<<<(H + 255) / 256, 256>>>(UBL + 2 * H, LBL + 2 * H,
                                    SUS + 2 * H, SUI + 2 * H, SLS + 2 * H, SLI + 2 * H,
                                    PUB + 2 * H, PLB + 2 * H);
    k_postspu<<<(H + 255) / 256, 256>>>(SUS + 2 * H, SUI + 2 * H, SLS + 2 * H, SLI + 2 * H,
                                        RAWV, RAWV + H, PUB + 2 * H, PLB + 2 * H);

    // ---- layer 4 (only the lower bound matters for the output) ----
    k_affine_interval<<<(DOUT + 7) / 8, 256>>>(w4, b4, PUB + 2 * H, PLB + 2 * H,
                                               UB4, LB4, H, DOUT);
    descend(w4, b4, DOUT, 0, 3, nullptr, LB4, nullptr);

    k_final_min<<<1, 32>>>(LB4, out);
}

// round 10
// speedup vs baseline: 1.4123x; 1.3579x over previous
#include <cuda_runtime.h>
#include <cuda_fp16.h>
#include <cstdint>
#include <math.h>

#define H    2048
#define DIN  784
#define DOUT 10
#define NPAD1 896                 // DIN padded to a multiple of 128

// ---------------- scratch (device globals; no allocations allowed) ----------------
__device__ __align__(256) float g_u0[DIN], g_l0[DIN];
__device__ __align__(256) float g_ubL[3 * H], g_lbL[3 * H];
__device__ __align__(256) float g_sus[3 * H], g_sui[3 * H];
__device__ __align__(256) float g_sls[3 * H], g_sli[3 * H];
__device__ __align__(256) float g_pub[3 * H], g_plb[3 * H];
__device__ __align__(256) float g_ub4[DOUT], g_lb4[DOUT];
__device__ __align__(256) float g_rawV[2 * H];                // raw descended values (u | l)
__device__ __align__(256) float g_W0[(long)2 * H * NPAD1];    // final-GEMM fp32 output
__device__ __align__(256) float g_Bias[2 * H];                // running chain bias
// fp16 split operand buffers (ping-pong A) + transposed fp16 weights (B)
__device__ __align__(256) __half g_Ahi[(long)2 * H * H];
__device__ __align__(256) __half g_Alo[(long)2 * H * H];
__device__ __align__(256) __half g_Ahi2[(long)2 * H * H];
__device__ __align__(256) __half g_Alo2[(long)2 * H * H];
__device__ __align__(256) __half g_T1f[(long)NPAD1 * H];
__device__ __align__(256) __half g_T2f[(long)H * H];
__device__ __align__(256) __half g_T3f[(long)H * H];

// ---------------- small device helpers ----------------
__device__ __forceinline__ float sigm_(float x) { return 1.0f / (1.0f + expf(-x)); }
__device__ __forceinline__ float spu_(float x) {
    return (x >= 0.0f) ? (x * x - 0.5f) : (sigm_(-x) - 1.0f);
}
__device__ __forceinline__ float warp_reduce(float v) {
#pragma unroll
    for (int o = 16; o > 0; o >>= 1) v += __shfl_down_sync(0xffffffffu, v, o);
    return v;
}
__device__ __forceinline__ uint32_t smem_u32(const void* p) {
    uint32_t a;
    asm("{ .reg .u64 t; cvta.to.shared.u64 t, %1; cvt.u32.u64 %0, t; }" : "=r"(a) : "l"(p));
    return a;
}
__device__ __forceinline__ void cp16(uint32_t dst, const void* src) {
    asm volatile("cp.async.cg.shared.global [%0], [%1], 16;" :: "r"(dst), "l"(src));
}
__device__ __forceinline__ void mma16816h(float* d, const uint32_t* a, const uint32_t* b) {
    asm volatile(
        "mma.sync.aligned.m16n8k16.row.col.f32.f16.f16.f32 "
        "{%0,%1,%2,%3}, {%4,%5,%6,%7}, {%8,%9}, {%0,%1,%2,%3};"
        : "+f"(d[0]), "+f"(d[1]), "+f"(d[2]), "+f"(d[3])
        : "r"(a[0]), "r"(a[1]), "r"(a[2]), "r"(a[3]), "r"(b[0]), "r"(b[1]));
}
__device__ __forceinline__ void ldsm_x4(uint32_t a, uint32_t* r) {
    asm volatile("ldmatrix.sync.aligned.m8n8.x4.shared.b16 {%0,%1,%2,%3}, [%4];"
                 : "=r"(r[0]), "=r"(r[1]), "=r"(r[2]), "=r"(r[3]) : "r"(a));
}
__device__ __forceinline__ void ldsm_x2(uint32_t a, uint32_t* r) {
    asm volatile("ldmatrix.sync.aligned.m8n8.x2.shared.b16 {%0,%1}, [%2];"
                 : "=r"(r[0]), "=r"(r[1]) : "r"(a));
}
// fp16 hi/lo split: hi = fp16(v), residual captured exactly enough (2^-22 total)
__device__ __forceinline__ __half2 split_h(float a, float b, float& ra, float& rb) {
    __half ha = __float2half_rn(a), hb = __float2half_rn(b);
    ra = a - __half2float(ha);
    rb = b - __half2float(hb);
    return __halves2half2(ha, hb);
}

// ---------------- elementwise kernels ----------------
__global__ void k_init_bounds(const float* __restrict__ in, const float* __restrict__ epsp,
                              float* __restrict__ u0, float* __restrict__ l0) {
    int i = blockIdx.x * blockDim.x + threadIdx.x;
    if (i >= DIN) return;
    float e = epsp[0];
    float u = fminf(in[i] + e, 1.0f);
    float l = fmaxf(in[i] - e, 0.0f);
    u0[i] = (u - 0.1307f) / 0.3081f;
    l0[i] = (l - 0.1307f) / 0.3081f;
}

// transpose to fp16: T[n][k] = (half)W[k][n]; rows n >= N (padding) are zero.
__global__ void k_transpose_f16(const float* __restrict__ W,
                                __half* __restrict__ T, int N) {
    __shared__ float t[32][33];
    int n0 = blockIdx.x * 32, k0 = blockIdx.y * 32;
    int tx = threadIdx.x, ty = threadIdx.y;
#pragma unroll
    for (int i = 0; i < 4; i++) {
        int k = k0 + ty + 8 * i;
        int n = n0 + tx;
        t[ty + 8 * i][tx] = (n < N) ? W[(long)k * N + n] : 0.0f;
    }
    __syncthreads();
#pragma unroll
    for (int i = 0; i < 4; i++) {
        int n = n0 + ty + 8 * i;
        int k = k0 + tx;
        T[(long)n * H + k] = __float2half_rn(t[tx][ty + 8 * i]);
    }
}

// interval bounds of W x + b; warp-per-row, 8 rows per block
__global__ __launch_bounds__(256) void k_affine_interval(
    const float* __restrict__ W, const float* __restrict__ b,
    const float* __restrict__ ub, const float* __restrict__ lb,
    float* __restrict__ uo, float* __restrict__ lo, int cols, int M) {
    int wid = threadIdx.x >> 5, lane = threadIdx.x & 31;
    int row = blockIdx.x * 8 + wid;
    if (row >= M) return;
    const float4* wr = (const float4*)(W + (long)row * cols);
    const float4* u4 = (const float4*)ub;
    const float4* l4 = (const float4*)lb;
    float su = 0.0f, sl = 0.0f;
    int c4 = cols >> 2;
    for (int j = lane; j < c4; j += 32) {
        float4 w = wr[j], u = u4[j], l = l4[j];
        float p, n;
        p = fmaxf(w.x, 0.0f); n = fminf(w.x, 0.0f); su += p * u.x + n * l.x; sl += p * l.x + n * u.x;
        p = fmaxf(w.y, 0.0f); n = fminf(w.y, 0.0f); su += p * u.y + n * l.y; sl += p * l.y + n * u.y;
        p = fmaxf(w.z, 0.0f); n = fminf(w.z, 0.0f); su += p * u.z + n * l.z; sl += p * l.z + n * u.z;
        p = fmaxf(w.w, 0.0f); n = fminf(w.w, 0.0f); su += p * u.w + n * l.w; sl += p * l.w + n * u.w;
    }
    su = warp_reduce(su);
    sl = warp_reduce(sl);
    if (lane == 0) { uo[row] = su + b[row]; lo[row] = sl + b[row]; }
}

// elementwise SPU relaxation analysis (exact reference math)
__global__ void k_spu(const float* __restrict__ ub, const float* __restrict__ lb,
                      float* __restrict__ us, float* __restrict__ ui,
                      float* __restrict__ ls, float* __restrict__ li,
                      float* __restrict__ pub, float* __restrict__ plb) {
    int i = blockIdx.x * blockDim.x + threadIdx.x;
    if (i >= H) return;
    float ux = ub[i], lx = lb[i];
    float uy = spu_(ux), ly = spu_(lx);
    float sj = (uy - ly) / (ux - lx);
    float ij = uy - sj * ux;
    bool right = lx > 0.0f;
    bool left  = ux <= 0.0f;
    float mid = 0.5f * (ux + lx);
    float sp = 2.0f * mid, ip = -mid * mid - 0.5f;
    float sm = sigm_(mid);
    float ssm = -sm * (1.0f - sm), ism = -sm - ssm * mid;
    float nub = fmaxf(uy, ly);
    float nlb, usv, uiv, lsv, liv;
    if (right) {
        usv = sj; uiv = ij; lsv = sp; liv = ip; nlb = fminf(uy, ly);
    } else if (left) {
        usv = ssm; uiv = ism; lsv = sj; liv = ij; nlb = fminf(uy, ly);
    } else {
        nlb = -0.5f;
        float spu2 = 2.0f * ux, ipu = -ux * ux - 0.5f;
        float limit = spu2 * lx + ipu;
        float clm = (fabsf(lx) > ux) ? 1.0f : 0.0f;
        float clp = sigm_((clm - 0.5f) * 10.0f) * (ly - limit) + limit;
        if (clp < -0.5f) {
            float D = 4.0f * lx * lx - 4.0f * clp - 2.0f;
            float x2 = (2.0f * lx + sqrtf(fmaxf(D, 0.0f))) * 0.5f;
            lsv = 2.0f * x2; liv = -x2 * x2 - 0.5f;
        } else {
            lsv = (-0.5f - clp) / (0.0f - lx); liv = -0.5f;
        }
        float sl_ = sigm_(lx);
        float ssl = -sl_ * (1.0f - sl_), isl = -sl_ - ssl * lx;
        float stv = ssl * ux + isl - uy;
        if (stv > 0.0f) {
            float L = lx, R = 0.0f;
#pragma unroll
            for (int t = 0; t < 10; t++) {
                float m = 0.5f * (L + R);
                float s = sigm_(m);
                float sms = -s * (1.0f - s), ims = -s - sms * m;
                bool mask = (sms * ux + ims - uy) > 0.0f;
                L = mask ? m : L;
                R = mask ? R : m;
            }
            float scp = sigm_(-5.0f) * (L - lx) + lx;
            float sc = sigm_(scp);
            usv = -sc * (1.0f - sc);
            uiv = -sc - usv * scp;
        } else {
            usv = sj; uiv = ij;
        }
    }
    us[i] = usv; ui[i] = uiv; ls[i] = lsv; li[i] = liv;
    pub[i] = nub; plb[i] = nlb;
}

// Post-SPU back-substitution collapse (exact identity)
__global__ void k_postspu(const float* __restrict__ sus, const float* __restrict__ sui,
                          const float* __restrict__ sls, const float* __restrict__ sli,
                          const float* __restrict__ rawVu, const float* __restrict__ rawVl,
                          float* __restrict__ pub, float* __restrict__ plb) {
    int i = blockIdx.x * blockDim.x + threadIdx.x;
    if (i >= H) return;
    float su = sus[i], iu = sui[i];
    float vu = (su >= 0.0f) ? rawVu[i] : rawVl[i];
    pub[i] = fminf(pub[i], su * vu + iu);
    float sl = sls[i], il = sli[i];
    float vl = (sl >= 0.0f) ? rawVl[i] : rawVu[i];
    plb[i] = fmaxf(plb[i], sl * vl + il);
}

// Chain-start column-scale from raw layer weights (upper rows [0,Mu), lower [Mu,M));
// emits fp16 hi/lo A operands and initializes the running chain bias.
__global__ __launch_bounds__(256) void k_colscale_start(
    const float* __restrict__ Wsrc, const float* __restrict__ bsrc,
    const float* __restrict__ sus, const float* __restrict__ sui,
    const float* __restrict__ sls, const float* __restrict__ sli,
    const float* __restrict__ blayer,
    __half* __restrict__ Ahi, __half* __restrict__ Alo,
    float* __restrict__ Bias, int M, int Mu) {
    int wid = threadIdx.x >> 5, lane = threadIdx.x & 31;
    int row = blockIdx.x * 8 + wid;
    if (row >= M) return;
    bool up = row < Mu;
    int orow = up ? row : row - Mu;
    const float4* ws = (const float4*)(Wsrc + (long)orow * H);
    __half2* ah = (__half2*)(Ahi + (long)row * H);
    __half2* al = (__half2*)(Alo + (long)row * H);
    const float4* ps = (const float4*)(up ? sus : sls);
    const float4* pi = (const float4*)(up ? sui : sli);
    const float4* ns = (const float4*)(up ? sls : sus);
    const float4* ni = (const float4*)(up ? sli : sui);
    const float4* bl = (const float4*)blayer;
    float acc = 0.0f;
#pragma unroll 4
    for (int j = lane; j < H / 4; j += 32) {
        float4 w = ws[j];
        float4 psv = ps[j], piv = pi[j], nsv = ns[j], niv = ni[j], blv = bl[j];
        float4 o;
        float p, n;
        p = fmaxf(w.x, 0.0f); n = fminf(w.x, 0.0f); o.x = p * psv.x + n * nsv.x; acc += p * piv.x + n * niv.x + o.x * blv.x;
        p = fmaxf(w.y, 0.0f); n = fminf(w.y, 0.0f); o.y = p * psv.y + n * nsv.y; acc += p * piv.y + n * niv.y + o.y * blv.y;
        p = fmaxf(w.z, 0.0f); n = fminf(w.z, 0.0f); o.z = p * psv.z + n * nsv.z; acc += p * piv.z + n * niv.z + o.z * blv.z;
        p = fmaxf(w.w, 0.0f); n = fminf(w.w, 0.0f); o.w = p * psv.w + n * nsv.w; acc += p * piv.w + n * niv.w + o.w * blv.w;
        float rx, ry, rz, rw;
        __half2 h01 = split_h(o.x, o.y, rx, ry);
        __half2 h23 = split_h(o.z, o.w, rz, rw);
        ah[2 * j]     = h01;
        ah[2 * j + 1] = h23;
        al[2 * j]     = __floats2half2_rn(rx, ry);
        al[2 * j + 1] = __floats2half2_rn(rz, rw);
    }
    acc = warp_reduce(acc);
    if (lane == 0) Bias[row] = bsrc[orow] + acc;
}

// Final interval evaluation at the input layer; warp-per-row.
__global__ __launch_bounds__(256) void k_interval_f(
    const float* __restrict__ W, int ld, const float* __restrict__ bias,
    const float* __restrict__ u0, const float* __restrict__ l0,
    float* __restrict__ ubio, float* __restrict__ lbio,
    float* __restrict__ rawV, int cols, int M, int Mu) {
    int wid = threadIdx.x >> 5, lane = threadIdx.x & 31;
    int row = blockIdx.x * 8 + wid;
    if (row >= M) return;
    bool up = row < Mu;
    int orow = up ? row : row - Mu;
    const float4* wr = (const float4*)(W + (long)row * ld);
    const float4* a4 = (const float4*)(up ? u0 : l0);
    const float4* c4p = (const float4*)(up ? l0 : u0);
    float acc = 0.0f;
    for (int j = lane; j < cols / 4; j += 32) {
        float4 w = wr[j];
        float4 av = a4[j], cv = c4p[j];
        acc += fmaxf(w.x, 0.0f) * av.x + fminf(w.x, 0.0f) * cv.x;
        acc += fmaxf(w.y, 0.0f) * av.y + fminf(w.y, 0.0f) * cv.y;
        acc += fmaxf(w.z, 0.0f) * av.z + fminf(w.z, 0.0f) * cv.z;
        acc += fmaxf(w.w, 0.0f) * av.w + fminf(w.w, 0.0f) * cv.w;
    }
    acc = warp_reduce(acc);
    if (lane == 0) {
        float v = acc + bias[row];
        if (rawV) rawV[row] = v;
        if (up) ubio[orow] = fminf(ubio[orow], v);
        else    lbio[orow] = fmaxf(lbio[orow], v);
    }
}

// ---------------- fp16 2-term split GEMM via mma.sync (HMMA) ----------------
// C = (Ahi + Alo) @ B^T with A hi/lo fp16 (split error 2^-22), B single fp16
// (weight perturbation 2^-11 — within the 1e-3 tolerance with margin).
#define GSTRIDE 80
#define TILEB   (128 * GSTRIDE)
#define STAGEB  (3 * TILEB)            // Ahi | Alo | B
#define GEMM_SMEM (2 * STAGEB)         // 61440

struct GemmCtx {
    float acc[4][4][4];
    int rowBase, colBase, mbase, nbase, lr, lc2;
};

__device__ __forceinline__ void gemm_mainloop(
    GemmCtx& cx, char* dynsm,
    const __half* __restrict__ Ahi, const __half* __restrict__ Alo,
    const __half* __restrict__ B, int M) {
    const int tid = threadIdx.x;
    const int wid = tid >> 5;
    const int lane = tid & 31;
    const uint32_t smbase = smem_u32(dynsm);
    const int wm = wid & 1, wn = wid >> 1;
    cx.mbase = wm * 64; cx.nbase = wn * 32;
    cx.lr = lane >> 2; cx.lc2 = 2 * (lane & 3);
#pragma unroll
    for (int mi = 0; mi < 4; mi++)
#pragma unroll
        for (int ni = 0; ni < 4; ni++)
#pragma unroll
            for (int t = 0; t < 4; t++) cx.acc[mi][ni][t] = 0.0f;

    const uint32_t aRowOff = (uint32_t)(cx.mbase + (lane & 15)) * GSTRIDE + (lane >> 4) * 16;
    const uint32_t bRowOff = (uint32_t)(cx.nbase + (lane & 7)) * GSTRIDE + ((lane >> 3) & 1) * 16;

    auto issue = [&](int c) {
        const int st = c & 1;
        const uint32_t base = smbase + st * STAGEB;
        const long k0 = (long)c * 32;
#pragma unroll
        for (int p = 0; p < 2; p++) {
            int u = tid + p * 256;
            int row = u >> 2, seg = u & 3;
            uint32_t so = base + row * GSTRIDE + seg * 16;
            long ka = k0 + seg * 8;
            int grow = cx.rowBase + row; if (grow > M - 1) grow = M - 1;
            cp16(so,             Ahi + (long)grow * H + ka);
            cp16(so + TILEB,     Alo + (long)grow * H + ka);
            int gn = cx.colBase + row;
            cp16(so + 2 * TILEB, B + (long)gn * H + ka);
        }
        asm volatile("cp.async.commit_group;");
    };

    issue(0);
    const int NK = H / 32;
    for (int c = 0; c < NK; ++c) {
        if (c + 1 < NK) {
            issue(c + 1);
            asm volatile("cp.async.wait_group 1;");
        } else {
            asm volatile("cp.async.wait_group 0;");
        }
        __syncthreads();
        const uint32_t sbu = smbase + (c & 1) * STAGEB;
        const uint32_t sAu = sbu + aRowOff;
        const uint32_t sBu = sbu + 2 * TILEB + bRowOff;
#pragma unroll
        for (int kk = 0; kk < 32; kk += 16) {
            const uint32_t kb = (uint32_t)(kk * 2);
            uint32_t bh[4][2];
#pragma unroll
            for (int ni = 0; ni < 4; ni++)
                ldsm_x2(sBu + (uint32_t)(ni * 8) * GSTRIDE + kb, bh[ni]);
#pragma unroll
            for (int mi = 0; mi < 4; mi++) {
                uint32_t pa = sAu + (uint32_t)(mi * 16) * GSTRIDE + kb;
                uint32_t ah[4], al[4];
                ldsm_x4(pa, ah);
                ldsm_x4(pa + TILEB, al);
#pragma unroll
                for (int ni = 0; ni < 4; ni++) {
                    mma16816h(cx.acc[mi][ni], ah, bh[ni]);
                    mma16816h(cx.acc[mi][ni], al, bh[ni]);
                }
            }
        }
        __syncthreads();
    }
}

// Plain epilogue: fp32 C (used for the last GEMM of a chain).
__global__ __launch_bounds__(256) void gemm_mma(
    const __half* __restrict__ Ahi, const __half* __restrict__ Alo,
    const __half* __restrict__ B,
    float* __restrict__ C, int M, int ldc) {
    extern __shared__ char dynsm[];
    GemmCtx cx;
    cx.rowBase = blockIdx.y * 128;
    cx.colBase = blockIdx.x * 128;
    gemm_mainloop(cx, dynsm, Ahi, Alo, B, M);
#pragma unroll
    for (int mi = 0; mi < 4; mi++) {
        int gr0 = cx.rowBase + cx.mbase + mi * 16 + cx.lr;
#pragma unroll
        for (int ni = 0; ni < 4; ni++) {
            int gc = cx.colBase + cx.nbase + ni * 8 + cx.lc2;
            if (gr0 < M) {
                float2 v = make_float2(cx.acc[mi][ni][0], cx.acc[mi][ni][1]);
                *(float2*)(C + (long)gr0 * ldc + gc) = v;
            }
            if (gr0 + 8 < M) {
                float2 v = make_float2(cx.acc[mi][ni][2], cx.acc[mi][ni][3]);
                *(float2*)(C + (long)(gr0 + 8) * ldc + gc) = v;
            }
        }
    }
}

// Fused colscale epilogue: applies the next SPU diagonal pass to the accumulators,
// writes fp16 hi/lo A operands for the next GEMM, and atomically accumulates the
// per-row bias contribution (quad-reduced) into the running chain bias.
__global__ __launch_bounds__(256) void gemm_mma_cs(
    const __half* __restrict__ Ahi, const __half* __restrict__ Alo,
    const __half* __restrict__ B,
    const float* __restrict__ sus, const float* __restrict__ sui,
    const float* __restrict__ sls, const float* __restrict__ sli,
    const float* __restrict__ blayer,
    __half* __restrict__ Aho, __half* __restrict__ Alo_o,
    float* __restrict__ Bias, int M, int Mu) {
    extern __shared__ char dynsm[];
    GemmCtx cx;
    cx.rowBase = blockIdx.y * 128;
    cx.colBase = blockIdx.x * 128;
    gemm_mainloop(cx, dynsm, Ahi, Alo, B, M);

    const bool up = cx.rowBase < Mu;    // Mu multiple of 128 (or 0) -> CTA-uniform
    const float* ps = up ? sus : sls;
    const float* pi = up ? sui : sli;
    const float* ns = up ? sls : sus;
    const float* ni_ = up ? sli : sui;
    const int lane = threadIdx.x & 31;

#pragma unroll
    for (int mi = 0; mi < 4; mi++) {
        int gr0 = cx.rowBase + cx.mbase + mi * 16 + cx.lr;
        int gr1 = gr0 + 8;
        float rs0 = 0.0f, rs1 = 0.0f;
#pragma unroll
        for (int ni = 0; ni < 4; ni++) {
            int gc = cx.colBase + cx.nbase + ni * 8 + cx.lc2;
            float s0 = ps[gc], s1 = ps[gc + 1];
            float i0 = pi[gc], i1 = pi[gc + 1];
            float t0 = ns[gc], t1 = ns[gc + 1];
            float u0v = ni_[gc], u1v = ni_[gc + 1];
            float b0 = blayer[gc], b1 = blayer[gc + 1];
            {
                float v0 = cx.acc[mi][ni][0], v1 = cx.acc[mi][ni][1];
                float p0 = fmaxf(v0, 0.0f), n0 = fminf(v0, 0.0f);
                float p1 = fmaxf(v1, 0.0f), n1 = fminf(v1, 0.0f);
                float o0 = p0 * s0 + n0 * t0;
                float o1 = p1 * s1 + n1 * t1;
                rs0 += p0 * i0 + n0 * u0v + o0 * b0 + p1 * i1 + n1 * u1v + o1 * b1;
                if (gr0 < M) {
                    float rx, ry;
                    __half2 hi2 = split_h(o0, o1, rx, ry);
                    *(__half2*)(Aho   + (long)gr0 * H + gc) = hi2;
                    *(__half2*)(Alo_o + (long)gr0 * H + gc) = __floats2half2_rn(rx, ry);
                }
            }
            {
                float v0 = cx.acc[mi][ni][2], v1 = cx.acc[mi][ni][3];
                float p0 = fmaxf(v0, 0.0f), n0 = fminf(v0, 0.0f);
                float p1 = fmaxf(v1, 0.0f), n1 = fminf(v1, 0.0f);
                float o0 = p0 * s0 + n0 * t0;
                float o1 = p1 * s1 + n1 * t1;
                rs1 += p0 * i0 + n0 * u0v + o0 * b0 + p1 * i1 + n1 * u1v + o1 * b1;
                if (gr1 < M) {
                    float rx, ry;
                    __half2 hi2 = split_h(o0, o1, rx, ry);
                    *(__half2*)(Aho   + (long)gr1 * H + gc) = hi2;
                    *(__half2*)(Alo_o + (long)gr1 * H + gc) = __floats2half2_rn(rx, ry);
                }
            }
        }
        rs0 += __shfl_xor_sync(0xffffffffu, rs0, 1);
        rs0 += __shfl_xor_sync(0xffffffffu, rs0, 2);
        rs1 += __shfl_xor_sync(0xffffffffu, rs1, 1);
        rs1 += __shfl_xor_sync(0xffffffffu, rs1, 2);
        if ((lane & 3) == 0) {
            if (gr0 < M) atomicAdd(Bias + gr0, rs0);
            if (gr1 < M) atomicAdd(Bias + gr1, rs1);
        }
    }
}

__global__ void k_final_min(const float* __restrict__ lb4, float* __restrict__ out) {
    if (threadIdx.x == 0) {
        float m = lb4[0];
#pragma unroll
        for (int i = 1; i < DOUT; i++) m = fminf(m, lb4[i]);
        out[0] = m;
    }
}

// ---------------- host orchestration ----------------
extern "C" void kernel_launch(void* const* d_in, const int* in_sizes, int n_in,
                              void* d_out, int out_size) {
    (void)in_sizes; (void)n_in; (void)out_size;
    const float* inputs = (const float*)d_in[0];
    const float* eps    = (const float*)d_in[1];
    const float* w1 = (const float*)d_in[2]; const float* b1 = (const float*)d_in[3];
    const float* w2 = (const float*)d_in[4]; const float* b2 = (const float*)d_in[5];
    const float* w3 = (const float*)d_in[6]; const float* b3 = (const float*)d_in[7];
    const float* w4 = (const float*)d_in[8]; const float* b4 = (const float*)d_in[9];
    float* out = (float*)d_out;

    cudaFuncSetAttribute(gemm_mma,    cudaFuncAttributeMaxDynamicSharedMemorySize, GEMM_SMEM);
    cudaFuncSetAttribute(gemm_mma_cs, cudaFuncAttributeMaxDynamicSharedMemorySize, GEMM_SMEM);

    float *U0, *L0, *UBL, *LBL, *SUS, *SUI, *SLS, *SLI, *PUB, *PLB, *UB4, *LB4, *RAWV;
    float *W0, *BIAS;
    __half *AHI, *ALO, *AH2, *AL2, *T1F, *T2F, *T3F;
    cudaGetSymbolAddress((void**)&U0, g_u0);
    cudaGetSymbolAddress((void**)&L0, g_l0);
    cudaGetSymbolAddress((void**)&UBL, g_ubL);
    cudaGetSymbolAddress((void**)&LBL, g_lbL);
    cudaGetSymbolAddress((void**)&SUS, g_sus);
    cudaGetSymbolAddress((void**)&SUI, g_sui);
    cudaGetSymbolAddress((void**)&SLS, g_sls);
    cudaGetSymbolAddress((void**)&SLI, g_sli);
    cudaGetSymbolAddress((void**)&PUB, g_pub);
    cudaGetSymbolAddress((void**)&PLB, g_plb);
    cudaGetSymbolAddress((void**)&UB4, g_ub4);
    cudaGetSymbolAddress((void**)&LB4, g_lb4);
    cudaGetSymbolAddress((void**)&RAWV, g_rawV);
    cudaGetSymbolAddress((void**)&W0, g_W0);
    cudaGetSymbolAddress((void**)&BIAS, g_Bias);
    cudaGetSymbolAddress((void**)&AHI, g_Ahi);
    cudaGetSymbolAddress((void**)&ALO, g_Alo);
    cudaGetSymbolAddress((void**)&AH2, g_Ahi2);
    cudaGetSymbolAddress((void**)&AL2, g_Alo2);
    cudaGetSymbolAddress((void**)&T1F, g_T1f);
    cudaGetSymbolAddress((void**)&T2F, g_T2f);
    cudaGetSymbolAddress((void**)&T3F, g_T3f);

    const float* LBv[3] = {b1, b2, b3};
    const __half* TF[3] = {T1F, T2F, T3F};

    // transposed fp16 weights (B operands)
    k_transpose_f16<<<dim3(NPAD1 / 32, H / 32), dim3(32, 8)>>>(w1, T1F, DIN);
    k_transpose_f16<<<dim3(H / 32, H / 32),     dim3(32, 8)>>>(w2, T2F, H);
    k_transpose_f16<<<dim3(H / 32, H / 32),     dim3(32, 8)>>>(w3, T3F, H);

    // Pre-SPU (first back-substitution) descend of W_lvl+1 down to the input box.
    auto descend = [&](const float* sW, const float* sB, int M, int Mu, int lvl,
                       float* ubio, float* lbio, float* rawV) {
        k_colscale_start<<<(M + 7) / 8, 256>>>(sW, sB,
                                               SUS + (lvl - 1) * H, SUI + (lvl - 1) * H,
                                               SLS + (lvl - 1) * H, SLI + (lvl - 1) * H,
                                               LBv[lvl - 1], AHI, ALO, BIAS, M, Mu);
        const __half *curH = AHI, *curL = ALO;
        __half *nxtH = AH2, *nxtL = AL2;
        for (int l = lvl; l >= 2; --l) {
            dim3 g(H / 128, (M + 127) / 128);
            gemm_mma_cs<<<g, 256, GEMM_SMEM>>>(curH, curL, TF[l - 1],
                                               SUS + (l - 2) * H, SUI + (l - 2) * H,
                                               SLS + (l - 2) * H, SLI + (l - 2) * H,
                                               LBv[l - 2], nxtH, nxtL, BIAS, M, Mu);
            const __half* th = curH; const __half* tl = curL;
            curH = nxtH; curL = nxtL;
            nxtH = (__half*)th; nxtL = (__half*)tl;
        }
        dim3 g(NPAD1 / 128, (M + 127) / 128);
        gemm_mma<<<g, 256, GEMM_SMEM>>>(curH, curL, TF[0], W0, M, NPAD1);
        k_interval_f<<<(M + 7) / 8, 256>>>(W0, NPAD1, BIAS, U0, L0, ubio, lbio, rawV,
                                           DIN, M, Mu);
    };

    // input box (normalized)
    k_init_bounds<<<(DIN + 255) / 256, 256>>>(inputs, eps, U0, L0);

    // ---- layer 1 ----
    k_affine_interval<<<H / 8, 256>>>(w1, b1, U0, L0, UBL + 0 * H, LBL + 0 * H, DIN, H);
    k_spu<<<(H + 255) / 256, 256>>>(UBL + 0 * H, LBL + 0 * H,
                                    SUS + 0 * H, SUI + 0 * H, SLS + 0 * H, SLI + 0 * H,
                                    PUB + 0 * H, PLB + 0 * H);
    k_postspu<<<(H + 255) / 256, 256>>>(SUS + 0 * H, SUI + 0 * H, SLS + 0 * H, SLI + 0 * H,
                                        UBL + 0 * H, LBL + 0 * H, PUB + 0 * H, PLB + 0 * H);

    // ---- layer 2 ----
    k_affine_interval<<<H / 8, 256>>>(w2, b2, PUB + 0 * H, PLB + 0 * H,
                                      UBL + 1 * H, LBL + 1 * H, H, H);
    descend(w2, b2, 2 * H, H, 1, UBL + 1 * H, LBL + 1 * H, RAWV);
    k_spu<<<(H + 255) / 256, 256>>>(UBL + 1 * H, LBL + 1 * H,
                                    SUS + 1 * H, SUI + 1 * H, SLS + 1 * H, SLI + 1 * H,
                                    PUB + 1 * H, PLB + 1 * H);
    k_postspu<<<(H + 255) / 256, 256>>>(SUS + 1 * H, SUI + 1 * H, SLS + 1 * H, SLI + 1 * H,
                                        RAWV, RAWV + H, PUB + 1 * H, PLB + 1 * H);

    // ---- layer 3 ----
    k_affine_interval<<<H / 8, 256>>>(w3, b3, PUB + 1 * H, PLB + 1 * H,
                                      UBL + 2 * H, LBL + 2 * H, H, H);
    descend(w3, b3, 2 * H, H, 2, UBL + 2 * H, LBL + 2 * H, RAWV);
    k_spu<<<(H + 255) / 256, 256>>>(UBL + 2 * H, LBL + 2 * H,
                                    SUS + 2 * H, SUI + 2 * H, SLS + 2 * H, SLI + 2 * H,
                                    PUB + 2 * H, PLB + 2 * H);
    k_postspu<<<(H + 255) / 256, 256>>>(SUS + 2 * H, SUI + 2 * H, SLS + 2 * H, SLI + 2 * H,
                                        RAWV, RAWV + H, PUB + 2 * H, PLB + 2 * H);

    // ---- layer 4 (only the lower bound matters for the output) ----
    k_affine_interval<<<(DOUT + 7) / 8, 256>>>(w4, b4, PUB + 2 * H, PLB + 2 * H,
                                               UB4, LB4, H, DOUT);
    descend(w4, b4, DOUT, 0, 3, nullptr, LB4, nullptr);

    k_final_min<<<1, 32>>>(LB4, out);
}

// round 11
// speedup vs baseline: 2.0522x; 1.4531x over previous
#include <cuda_runtime.h>
#include <cuda_fp16.h>
#include <cstdint>
#include <math.h>

#define H    2048
#define DIN  784
#define DOUT 10
#define NPAD1 896                 // DIN padded to a multiple of 128

// ---------------- scratch (device globals; no allocations allowed) ----------------
__device__ __align__(256) float g_u0[DIN], g_l0[DIN];
__device__ __align__(256) float g_ubL[3 * H], g_lbL[3 * H];
__device__ __align__(256) float g_sus[3 * H], g_sui[3 * H];
__device__ __align__(256) float g_sls[3 * H], g_sli[3 * H];
__device__ __align__(256) float g_pub[3 * H], g_plb[3 * H];
__device__ __align__(256) float g_ub4[DOUT], g_lb4[DOUT];
__device__ __align__(256) float g_rawV[2 * H];                // raw descended values (u | l)
__device__ __align__(256) float g_W0[(long)2 * H * NPAD1];    // final-GEMM fp32 output
__device__ __align__(256) float g_Bias[2 * H];                // running chain bias
// fp16 operand buffers (ping-pong A) + transposed fp16 weights (B)
__device__ __align__(256) __half g_A1[(long)2 * H * H];
__device__ __align__(256) __half g_A2[(long)2 * H * H];
__device__ __align__(256) __half g_T1f[(long)NPAD1 * H];
__device__ __align__(256) __half g_T2f[(long)H * H];
__device__ __align__(256) __half g_T3f[(long)H * H];

// ---------------- small device helpers ----------------
__device__ __forceinline__ float sigm_(float x) { return 1.0f / (1.0f + expf(-x)); }
__device__ __forceinline__ float spu_(float x) {
    return (x >= 0.0f) ? (x * x - 0.5f) : (sigm_(-x) - 1.0f);
}
__device__ __forceinline__ float warp_reduce(float v) {
#pragma unroll
    for (int o = 16; o > 0; o >>= 1) v += __shfl_down_sync(0xffffffffu, v, o);
    return v;
}
__device__ __forceinline__ uint32_t smem_u32(const void* p) {
    uint32_t a;
    asm("{ .reg .u64 t; cvta.to.shared.u64 t, %1; cvt.u32.u64 %0, t; }" : "=r"(a) : "l"(p));
    return a;
}
__device__ __forceinline__ void cp16(uint32_t dst, const void* src) {
    asm volatile("cp.async.cg.shared.global [%0], [%1], 16;" :: "r"(dst), "l"(src));
}
__device__ __forceinline__ void mma16816h(float* d, const uint32_t* a, const uint32_t* b) {
    asm volatile(
        "mma.sync.aligned.m16n8k16.row.col.f32.f16.f16.f32 "
        "{%0,%1,%2,%3}, {%4,%5,%6,%7}, {%8,%9}, {%0,%1,%2,%3};"
        : "+f"(d[0]), "+f"(d[1]), "+f"(d[2]), "+f"(d[3])
        : "r"(a[0]), "r"(a[1]), "r"(a[2]), "r"(a[3]), "r"(b[0]), "r"(b[1]));
}
__device__ __forceinline__ void ldsm_x4(uint32_t a, uint32_t* r) {
    asm volatile("ldmatrix.sync.aligned.m8n8.x4.shared.b16 {%0,%1,%2,%3}, [%4];"
                 : "=r"(r[0]), "=r"(r[1]), "=r"(r[2]), "=r"(r[3]) : "r"(a));
}
__device__ __forceinline__ void ldsm_x2(uint32_t a, uint32_t* r) {
    asm volatile("ldmatrix.sync.aligned.m8n8.x2.shared.b16 {%0,%1}, [%2];"
                 : "=r"(r[0]), "=r"(r[1]) : "r"(a));
}

// ---------------- elementwise kernels ----------------
__global__ void k_init_bounds(const float* __restrict__ in, const float* __restrict__ epsp,
                              float* __restrict__ u0, float* __restrict__ l0) {
    int i = blockIdx.x * blockDim.x + threadIdx.x;
    if (i >= DIN) return;
    float e = epsp[0];
    float u = fminf(in[i] + e, 1.0f);
    float l = fmaxf(in[i] - e, 0.0f);
    u0[i] = (u - 0.1307f) / 0.3081f;
    l0[i] = (l - 0.1307f) / 0.3081f;
}

// transpose to fp16: T[n][k] = (half)W[k][n]; rows n >= N (padding) are zero.
__global__ void k_transpose_f16(const float* __restrict__ W,
                                __half* __restrict__ T, int N) {
    __shared__ float t[32][33];
    int n0 = blockIdx.x * 32, k0 = blockIdx.y * 32;
    int tx = threadIdx.x, ty = threadIdx.y;
#pragma unroll
    for (int i = 0; i < 4; i++) {
        int k = k0 + ty + 8 * i;
        int n = n0 + tx;
        t[ty + 8 * i][tx] = (n < N) ? W[(long)k * N + n] : 0.0f;
    }
    __syncthreads();
#pragma unroll
    for (int i = 0; i < 4; i++) {
        int n = n0 + ty + 8 * i;
        int k = k0 + tx;
        T[(long)n * H + k] = __float2half_rn(t[tx][ty + 8 * i]);
    }
}

// interval bounds of W x + b; warp-per-row, 8 rows per block
__global__ __launch_bounds__(256) void k_affine_interval(
    const float* __restrict__ W, const float* __restrict__ b,
    const float* __restrict__ ub, const float* __restrict__ lb,
    float* __restrict__ uo, float* __restrict__ lo, int cols, int M) {
    int wid = threadIdx.x >> 5, lane = threadIdx.x & 31;
    int row = blockIdx.x * 8 + wid;
    if (row >= M) return;
    const float4* wr = (const float4*)(W + (long)row * cols);
    const float4* u4 = (const float4*)ub;
    const float4* l4 = (const float4*)lb;
    float su = 0.0f, sl = 0.0f;
    int c4 = cols >> 2;
    for (int j = lane; j < c4; j += 32) {
        float4 w = wr[j], u = u4[j], l = l4[j];
        float p, n;
        p = fmaxf(w.x, 0.0f); n = fminf(w.x, 0.0f); su += p * u.x + n * l.x; sl += p * l.x + n * u.x;
        p = fmaxf(w.y, 0.0f); n = fminf(w.y, 0.0f); su += p * u.y + n * l.y; sl += p * l.y + n * u.y;
        p = fmaxf(w.z, 0.0f); n = fminf(w.z, 0.0f); su += p * u.z + n * l.z; sl += p * l.z + n * u.z;
        p = fmaxf(w.w, 0.0f); n = fminf(w.w, 0.0f); su += p * u.w + n * l.w; sl += p * l.w + n * u.w;
    }
    su = warp_reduce(su);
    sl = warp_reduce(sl);
    if (lane == 0) { uo[row] = su + b[row]; lo[row] = sl + b[row]; }
}

// elementwise SPU relaxation analysis (exact reference math)
__global__ void k_spu(const float* __restrict__ ub, const float* __restrict__ lb,
                      float* __restrict__ us, float* __restrict__ ui,
                      float* __restrict__ ls, float* __restrict__ li,
                      float* __restrict__ pub, float* __restrict__ plb) {
    int i = blockIdx.x * blockDim.x + threadIdx.x;
    if (i >= H) return;
    float ux = ub[i], lx = lb[i];
    float uy = spu_(ux), ly = spu_(lx);
    float sj = (uy - ly) / (ux - lx);
    float ij = uy - sj * ux;
    bool right = lx > 0.0f;
    bool left  = ux <= 0.0f;
    float mid = 0.5f * (ux + lx);
    float sp = 2.0f * mid, ip = -mid * mid - 0.5f;
    float sm = sigm_(mid);
    float ssm = -sm * (1.0f - sm), ism = -sm - ssm * mid;
    float nub = fmaxf(uy, ly);
    float nlb, usv, uiv, lsv, liv;
    if (right) {
        usv = sj; uiv = ij; lsv = sp; liv = ip; nlb = fminf(uy, ly);
    } else if (left) {
        usv = ssm; uiv = ism; lsv = sj; liv = ij; nlb = fminf(uy, ly);
    } else {
        nlb = -0.5f;
        float spu2 = 2.0f * ux, ipu = -ux * ux - 0.5f;
        float limit = spu2 * lx + ipu;
        float clm = (fabsf(lx) > ux) ? 1.0f : 0.0f;
        float clp = sigm_((clm - 0.5f) * 10.0f) * (ly - limit) + limit;
        if (clp < -0.5f) {
            float D = 4.0f * lx * lx - 4.0f * clp - 2.0f;
            float x2 = (2.0f * lx + sqrtf(fmaxf(D, 0.0f))) * 0.5f;
            lsv = 2.0f * x2; liv = -x2 * x2 - 0.5f;
        } else {
            lsv = (-0.5f - clp) / (0.0f - lx); liv = -0.5f;
        }
        float sl_ = sigm_(lx);
        float ssl = -sl_ * (1.0f - sl_), isl = -sl_ - ssl * lx;
        float stv = ssl * ux + isl - uy;
        if (stv > 0.0f) {
            float L = lx, R = 0.0f;
#pragma unroll
            for (int t = 0; t < 10; t++) {
                float m = 0.5f * (L + R);
                float s = sigm_(m);
                float sms = -s * (1.0f - s), ims = -s - sms * m;
                bool mask = (sms * ux + ims - uy) > 0.0f;
                L = mask ? m : L;
                R = mask ? R : m;
            }
            float scp = sigm_(-5.0f) * (L - lx) + lx;
            float sc = sigm_(scp);
            usv = -sc * (1.0f - sc);
            uiv = -sc - usv * scp;
        } else {
            usv = sj; uiv = ij;
        }
    }
    us[i] = usv; ui[i] = uiv; ls[i] = lsv; li[i] = liv;
    pub[i] = nub; plb[i] = nlb;
}

// Post-SPU back-substitution collapse (exact identity)
__global__ void k_postspu(const float* __restrict__ sus, const float* __restrict__ sui,
                          const float* __restrict__ sls, const float* __restrict__ sli,
                          const float* __restrict__ rawVu, const float* __restrict__ rawVl,
                          float* __restrict__ pub, float* __restrict__ plb) {
    int i = blockIdx.x * blockDim.x + threadIdx.x;
    if (i >= H) return;
    float su = sus[i], iu = sui[i];
    float vu = (su >= 0.0f) ? rawVu[i] : rawVl[i];
    pub[i] = fminf(pub[i], su * vu + iu);
    float sl = sls[i], il = sli[i];
    float vl = (sl >= 0.0f) ? rawVl[i] : rawVu[i];
    plb[i] = fmaxf(plb[i], sl * vl + il);
}

// Chain-start column-scale from raw layer weights (upper rows [0,Mu), lower [Mu,M));
// emits fp16 A operand and initializes the running chain bias.
__global__ __launch_bounds__(256) void k_colscale_start(
    const float* __restrict__ Wsrc, const float* __restrict__ bsrc,
    const float* __restrict__ sus, const float* __restrict__ sui,
    const float* __restrict__ sls, const float* __restrict__ sli,
    const float* __restrict__ blayer,
    __half* __restrict__ A, float* __restrict__ Bias, int M, int Mu) {
    int wid = threadIdx.x >> 5, lane = threadIdx.x & 31;
    int row = blockIdx.x * 8 + wid;
    if (row >= M) return;
    bool up = row < Mu;
    int orow = up ? row : row - Mu;
    const float4* ws = (const float4*)(Wsrc + (long)orow * H);
    __half2* ah = (__half2*)(A + (long)row * H);
    const float4* ps = (const float4*)(up ? sus : sls);
    const float4* pi = (const float4*)(up ? sui : sli);
    const float4* ns = (const float4*)(up ? sls : sus);
    const float4* ni = (const float4*)(up ? sli : sui);
    const float4* bl = (const float4*)blayer;
    float acc = 0.0f;
#pragma unroll 4
    for (int j = lane; j < H / 4; j += 32) {
        float4 w = ws[j];
        float4 psv = ps[j], piv = pi[j], nsv = ns[j], niv = ni[j], blv = bl[j];
        float4 o;
        float p, n;
        p = fmaxf(w.x, 0.0f); n = fminf(w.x, 0.0f); o.x = p * psv.x + n * nsv.x; acc += p * piv.x + n * niv.x + o.x * blv.x;
        p = fmaxf(w.y, 0.0f); n = fminf(w.y, 0.0f); o.y = p * psv.y + n * nsv.y; acc += p * piv.y + n * niv.y + o.y * blv.y;
        p = fmaxf(w.z, 0.0f); n = fminf(w.z, 0.0f); o.z = p * psv.z + n * nsv.z; acc += p * piv.z + n * niv.z + o.z * blv.z;
        p = fmaxf(w.w, 0.0f); n = fminf(w.w, 0.0f); o.w = p * psv.w + n * nsv.w; acc += p * piv.w + n * niv.w + o.w * blv.w;
        ah[2 * j]     = __floats2half2_rn(o.x, o.y);
        ah[2 * j + 1] = __floats2half2_rn(o.z, o.w);
    }
    acc = warp_reduce(acc);
    if (lane == 0) Bias[row] = bsrc[orow] + acc;
}

// Final interval evaluation at the input layer; warp-per-row.
__global__ __launch_bounds__(256) void k_interval_f(
    const float* __restrict__ W, int ld, const float* __restrict__ bias,
    const float* __restrict__ u0, const float* __restrict__ l0,
    float* __restrict__ ubio, float* __restrict__ lbio,
    float* __restrict__ rawV, int cols, int M, int Mu) {
    int wid = threadIdx.x >> 5, lane = threadIdx.x & 31;
    int row = blockIdx.x * 8 + wid;
    if (row >= M) return;
    bool up = row < Mu;
    int orow = up ? row : row - Mu;
    const float4* wr = (const float4*)(W + (long)row * ld);
    const float4* a4 = (const float4*)(up ? u0 : l0);
    const float4* c4p = (const float4*)(up ? l0 : u0);
    float acc = 0.0f;
    for (int j = lane; j < cols / 4; j += 32) {
        float4 w = wr[j];
        float4 av = a4[j], cv = c4p[j];
        acc += fmaxf(w.x, 0.0f) * av.x + fminf(w.x, 0.0f) * cv.x;
        acc += fmaxf(w.y, 0.0f) * av.y + fminf(w.y, 0.0f) * cv.y;
        acc += fmaxf(w.z, 0.0f) * av.z + fminf(w.z, 0.0f) * cv.z;
        acc += fmaxf(w.w, 0.0f) * av.w + fminf(w.w, 0.0f) * cv.w;
    }
    acc = warp_reduce(acc);
    if (lane == 0) {
        float v = acc + bias[row];
        if (rawV) rawV[row] = v;
        if (up) ubio[orow] = fminf(ubio[orow], v);
        else    lbio[orow] = fmaxf(lbio[orow], v);
    }
}

// ---------------- fp16 GEMM via mma.sync (HMMA), 3-stage cp.async pipeline ------
// C = A @ B^T, A fp16 (rounding errors cancel ~sqrt(K)-fold over K=2048),
// B fp16 (same argument; measured chain amplification ~1).
#define GSTRIDE 80
#define TILEB   (128 * GSTRIDE)
#define STAGEB  (2 * TILEB)            // A | B
#define NSTAGE  3
#define GEMM_SMEM (NSTAGE * STAGEB)    // 61440

struct GemmCtx {
    float acc[4][4][4];
    int rowBase, colBase, mbase, nbase, lr, lc2;
};

__device__ __forceinline__ void gemm_mainloop(
    GemmCtx& cx, char* dynsm,
    const __half* __restrict__ A, const __half* __restrict__ B, int M) {
    const int tid = threadIdx.x;
    const int wid = tid >> 5;
    const int lane = tid & 31;
    const uint32_t smbase = smem_u32(dynsm);
    const int wm = wid & 1, wn = wid >> 1;
    cx.mbase = wm * 64; cx.nbase = wn * 32;
    cx.lr = lane >> 2; cx.lc2 = 2 * (lane & 3);
#pragma unroll
    for (int mi = 0; mi < 4; mi++)
#pragma unroll
        for (int ni = 0; ni < 4; ni++)
#pragma unroll
            for (int t = 0; t < 4; t++) cx.acc[mi][ni][t] = 0.0f;

    const uint32_t aRowOff = (uint32_t)(cx.mbase + (lane & 15)) * GSTRIDE + (lane >> 4) * 16;
    const uint32_t bRowOff = (uint32_t)(cx.nbase + (lane & 7)) * GSTRIDE + ((lane >> 3) & 1) * 16;

    // per-thread load slot: 512 (row, seg) pairs over 2 iterations of 256 threads
    auto issue = [&](int c) {
        const int st = c % NSTAGE;
        const uint32_t base = smbase + st * STAGEB;
        const long k0 = (long)c * 32;
#pragma unroll
        for (int p = 0; p < 2; p++) {
            int u = tid + p * 256;
            int row = u >> 2, seg = u & 3;
            uint32_t so = base + row * GSTRIDE + seg * 16;
            long ka = k0 + seg * 8;
            int grow = cx.rowBase + row; if (grow > M - 1) grow = M - 1;
            cp16(so,         A + (long)grow * H + ka);
            int gn = cx.colBase + row;
            cp16(so + TILEB, B + (long)gn * H + ka);
        }
        asm volatile("cp.async.commit_group;");
    };

    const int NK = H / 32;
    issue(0);
    issue(1);
    for (int c = 0; c < NK; ++c) {
        if (c + 2 < NK) {
            issue(c + 2);
            asm volatile("cp.async.wait_group 2;");
        } else if (c + 1 < NK) {
            asm volatile("cp.async.wait_group 1;");
        } else {
            asm volatile("cp.async.wait_group 0;");
        }
        __syncthreads();
        const uint32_t sbu = smbase + (c % NSTAGE) * STAGEB;
        const uint32_t sAu = sbu + aRowOff;
        const uint32_t sBu = sbu + TILEB + bRowOff;
#pragma unroll
        for (int kk = 0; kk < 32; kk += 16) {
            const uint32_t kb = (uint32_t)(kk * 2);
            uint32_t bh[4][2];
#pragma unroll
            for (int ni = 0; ni < 4; ni++)
                ldsm_x2(sBu + (uint32_t)(ni * 8) * GSTRIDE + kb, bh[ni]);
#pragma unroll
            for (int mi = 0; mi < 4; mi++) {
                uint32_t ah[4];
                ldsm_x4(sAu + (uint32_t)(mi * 16) * GSTRIDE + kb, ah);
#pragma unroll
                for (int ni = 0; ni < 4; ni++)
                    mma16816h(cx.acc[mi][ni], ah, bh[ni]);
            }
        }
        __syncthreads();
    }
}

// Plain epilogue: fp32 C (used for the last GEMM of a chain).
__global__ __launch_bounds__(256) void gemm_mma(
    const __half* __restrict__ A, const __half* __restrict__ B,
    float* __restrict__ C, int M, int ldc) {
    extern __shared__ char dynsm[];
    GemmCtx cx;
    cx.rowBase = blockIdx.y * 128;
    cx.colBase = blockIdx.x * 128;
    gemm_mainloop(cx, dynsm, A, B, M);
#pragma unroll
    for (int mi = 0; mi < 4; mi++) {
        int gr0 = cx.rowBase + cx.mbase + mi * 16 + cx.lr;
#pragma unroll
        for (int ni = 0; ni < 4; ni++) {
            int gc = cx.colBase + cx.nbase + ni * 8 + cx.lc2;
            if (gr0 < M) {
                float2 v = make_float2(cx.acc[mi][ni][0], cx.acc[mi][ni][1]);
                *(float2*)(C + (long)gr0 * ldc + gc) = v;
            }
            if (gr0 + 8 < M) {
                float2 v = make_float2(cx.acc[mi][ni][2], cx.acc[mi][ni][3]);
                *(float2*)(C + (long)(gr0 + 8) * ldc + gc) = v;
            }
        }
    }
}

// Fused colscale epilogue: applies the next SPU diagonal pass to the accumulators,
// writes the fp16 A operand for the next GEMM, and atomically accumulates the
// per-row bias contribution (quad-reduced) into the running chain bias.
__global__ __launch_bounds__(256) void gemm_mma_cs(
    const __half* __restrict__ A, const __half* __restrict__ B,
    const float* __restrict__ sus, const float* __restrict__ sui,
    const float* __restrict__ sls, const float* __restrict__ sli,
    const float* __restrict__ blayer,
    __half* __restrict__ Ao, float* __restrict__ Bias, int M, int Mu) {
    extern __shared__ char dynsm[];
    GemmCtx cx;
    cx.rowBase = blockIdx.y * 128;
    cx.colBase = blockIdx.x * 128;
    gemm_mainloop(cx, dynsm, A, B, M);

    const bool up = cx.rowBase < Mu;    // Mu multiple of 128 (or 0) -> CTA-uniform
    const float* ps = up ? sus : sls;
    const float* pi = up ? sui : sli;
    const float* ns = up ? sls : sus;
    const float* ni_ = up ? sli : sui;
    const int lane = threadIdx.x & 31;

#pragma unroll
    for (int mi = 0; mi < 4; mi++) {
        int gr0 = cx.rowBase + cx.mbase + mi * 16 + cx.lr;
        int gr1 = gr0 + 8;
        float rs0 = 0.0f, rs1 = 0.0f;
#pragma unroll
        for (int ni = 0; ni < 4; ni++) {
            int gc = cx.colBase + cx.nbase + ni * 8 + cx.lc2;
            float s0 = ps[gc], s1 = ps[gc + 1];
            float i0 = pi[gc], i1 = pi[gc + 1];
            float t0 = ns[gc], t1 = ns[gc + 1];
            float u0v = ni_[gc], u1v = ni_[gc + 1];
            float b0 = blayer[gc], b1 = blayer[gc + 1];
            {
                float v0 = cx.acc[mi][ni][0], v1 = cx.acc[mi][ni][1];
                float p0 = fmaxf(v0, 0.0f), n0 = fminf(v0, 0.0f);
                float p1 = fmaxf(v1, 0.0f), n1 = fminf(v1, 0.0f);
                float o0 = p0 * s0 + n0 * t0;
                float o1 = p1 * s1 + n1 * t1;
                rs0 += p0 * i0 + n0 * u0v + o0 * b0 + p1 * i1 + n1 * u1v + o1 * b1;
                if (gr0 < M)
                    *(__half2*)(Ao + (long)gr0 * H + gc) = __floats2half2_rn(o0, o1);
            }
            {
                float v0 = cx.acc[mi][ni][2], v1 = cx.acc[mi][ni][3];
                float p0 = fmaxf(v0, 0.0f), n0 = fminf(v0, 0.0f);
                float p1 = fmaxf(v1, 0.0f), n1 = fminf(v1, 0.0f);
                float o0 = p0 * s0 + n0 * t0;
                float o1 = p1 * s1 + n1 * t1;
                rs1 += p0 * i0 + n0 * u0v + o0 * b0 + p1 * i1 + n1 * u1v + o1 * b1;
                if (gr1 < M)
                    *(__half2*)(Ao + (long)gr1 * H + gc) = __floats2half2_rn(o0, o1);
            }
        }
        rs0 += __shfl_xor_sync(0xffffffffu, rs0, 1);
        rs0 += __shfl_xor_sync(0xffffffffu, rs0, 2);
        rs1 += __shfl_xor_sync(0xffffffffu, rs1, 1);
        rs1 += __shfl_xor_sync(0xffffffffu, rs1, 2);
        if ((lane & 3) == 0) {
            if (gr0 < M) atomicAdd(Bias + gr0, rs0);
            if (gr1 < M) atomicAdd(Bias + gr1, rs1);
        }
    }
}

__global__ void k_final_min(const float* __restrict__ lb4, float* __restrict__ out) {
    if (threadIdx.x == 0) {
        float m = lb4[0];
#pragma unroll
        for (int i = 1; i < DOUT; i++) m = fminf(m, lb4[i]);
        out[0] = m;
    }
}

// ---------------- host orchestration ----------------
extern "C" void kernel_launch(void* const* d_in, const int* in_sizes, int n_in,
                              void* d_out, int out_size) {
    (void)in_sizes; (void)n_in; (void)out_size;
    const float* inputs = (const float*)d_in[0];
    const float* eps    = (const float*)d_in[1];
    const float* w1 = (const float*)d_in[2]; const float* b1 = (const float*)d_in[3];
    const float* w2 = (const float*)d_in[4]; const float* b2 = (const float*)d_in[5];
    const float* w3 = (const float*)d_in[6]; const float* b3 = (const float*)d_in[7];
    const float* w4 = (const float*)d_in[8]; const float* b4 = (const float*)d_in[9];
    float* out = (float*)d_out;

    cudaFuncSetAttribute(gemm_mma,    cudaFuncAttributeMaxDynamicSharedMemorySize, GEMM_SMEM);
    cudaFuncSetAttribute(gemm_mma_cs, cudaFuncAttributeMaxDynamicSharedMemorySize, GEMM_SMEM);

    float *U0, *L0, *UBL, *LBL, *SUS, *SUI, *SLS, *SLI, *PUB, *PLB, *UB4, *LB4, *RAWV;
    float *W0, *BIAS;
    __half *A1, *A2, *T1F, *T2F, *T3F;
    cudaGetSymbolAddress((void**)&U0, g_u0);
    cudaGetSymbolAddress((void**)&L0, g_l0);
    cudaGetSymbolAddress((void**)&UBL, g_ubL);
    cudaGetSymbolAddress((void**)&LBL, g_lbL);
    cudaGetSymbolAddress((void**)&SUS, g_sus);
    cudaGetSymbolAddress((void**)&SUI, g_sui);
    cudaGetSymbolAddress((void**)&SLS, g_sls);
    cudaGetSymbolAddress((void**)&SLI, g_sli);
    cudaGetSymbolAddress((void**)&PUB, g_pub);
    cudaGetSymbolAddress((void**)&PLB, g_plb);
    cudaGetSymbolAddress((void**)&UB4, g_ub4);
    cudaGetSymbolAddress((void**)&LB4, g_lb4);
    cudaGetSymbolAddress((void**)&RAWV, g_rawV);
    cudaGetSymbolAddress((void**)&W0, g_W0);
    cudaGetSymbolAddress((void**)&BIAS, g_Bias);
    cudaGetSymbolAddress((void**)&A1, g_A1);
    cudaGetSymbolAddress((void**)&A2, g_A2);
    cudaGetSymbolAddress((void**)&T1F, g_T1f);
    cudaGetSymbolAddress((void**)&T2F, g_T2f);
    cudaGetSymbolAddress((void**)&T3F, g_T3f);

    const float* LBv[3] = {b1, b2, b3};
    const __half* TF[3] = {T1F, T2F, T3F};

    // transposed fp16 weights (B operands)
    k_transpose_f16<<<dim3(NPAD1 / 32, H / 32), dim3(32, 8)>>>(w1, T1F, DIN);
    k_transpose_f16<<<dim3(H / 32, H / 32),     dim3(32, 8)>>>(w2, T2F, H);
    k_transpose_f16<<<dim3(H / 32, H / 32),     dim3(32, 8)>>>(w3, T3F, H);

    // Pre-SPU (first back-substitution) descend of W_lvl+1 down to the input box.
    auto descend = [&](const float* sW, const float* sB, int M, int Mu, int lvl,
                       float* ubio, float* lbio, float* rawV) {
        k_colscale_start<<<(M + 7) / 8, 256>>>(sW, sB,
                                               SUS + (lvl - 1) * H, SUI + (lvl - 1) * H,
                                               SLS + (lvl - 1) * H, SLI + (lvl - 1) * H,
                                               LBv[lvl - 1], A1, BIAS, M, Mu);
        const __half* curA = A1;
        __half* nxtA = A2;
        for (int l = lvl; l >= 2; --l) {
            dim3 g(H / 128, (M + 127) / 128);
            gemm_mma_cs<<<g, 256, GEMM_SMEM>>>(curA, TF[l - 1],
                                               SUS + (l - 2) * H, SUI + (l - 2) * H,
                                               SLS + (l - 2) * H, SLI + (l - 2) * H,
                                               LBv[l - 2], nxtA, BIAS, M, Mu);
            const __half* t = curA;
            curA = nxtA;
            nxtA = (__half*)t;
        }
        dim3 g(NPAD1 / 128, (M + 127) / 128);
        gemm_mma<<<g, 256, GEMM_SMEM>>>(curA, TF[0], W0, M, NPAD1);
        k_interval_f<<<(M + 7) / 8, 256>>>(W0, NPAD1, BIAS, U0, L0, ubio, lbio, rawV,
                                           DIN, M, Mu);
    };

    // input box (normalized)
    k_init_bounds<<<(DIN + 255) / 256, 256>>>(inputs, eps, U0, L0);

    // ---- layer 1 ----
    k_affine_interval<<<H / 8, 256>>>(w1, b1, U0, L0, UBL + 0 * H, LBL + 0 * H, DIN, H);
    k_spu<<<(H + 255) / 256, 256>>>(UBL + 0 * H, LBL + 0 * H,
                                    SUS + 0 * H, SUI + 0 * H, SLS + 0 * H, SLI + 0 * H,
                                    PUB + 0 * H, PLB + 0 * H);
    k_postspu<<<(H + 255) / 256, 256>>>(SUS + 0 * H, SUI + 0 * H, SLS + 0 * H, SLI + 0 * H,
                                        UBL + 0 * H, LBL + 0 * H, PUB + 0 * H, PLB + 0 * H);

    // ---- layer 2 ----
    k_affine_interval<<<H / 8, 256>>>(w2, b2, PUB + 0 * H, PLB + 0 * H,
                                      UBL + 1 * H, LBL + 1 * H, H, H);
    descend(w2, b2, 2 * H, H, 1, UBL + 1 * H, LBL + 1 * H, RAWV);
    k_spu<<<(H + 255) / 256, 256>>>(UBL + 1 * H, LBL + 1 * H,
                                    SUS + 1 * H, SUI + 1 * H, SLS + 1 * H, SLI + 1 * H,
                                    PUB + 1 * H, PLB + 1 * H);
    k_postspu<<<(H + 255) / 256, 256>>>(SUS + 1 * H, SUI + 1 * H, SLS + 1 * H, SLI + 1 * H,
                                        RAWV, RAWV + H, PUB + 1 * H, PLB + 1 * H);

    // ---- layer 3 ----
    k_affine_interval<<<H / 8, 256>>>(w3, b3, PUB + 1 * H, PLB + 1 * H,
                                      UBL + 2 * H, LBL + 2 * H, H, H);
    descend(w3, b3, 2 * H, H, 2, UBL + 2 * H, LBL + 2 * H, RAWV);
    k_spu<<<(H + 255) / 256, 256>>>(UBL + 2 * H, LBL + 2 * H,
                                    SUS + 2 * H, SUI + 2 * H, SLS + 2 * H, SLI + 2 * H,
                                    PUB + 2 * H, PLB + 2 * H);
    k_postspu<<<(H + 255) / 256, 256>>>(SUS + 2 * H, SUI + 2 * H, SLS + 2 * H, SLI + 2 * H,
                                        RAWV, RAWV + H, PUB + 2 * H, PLB + 2 * H);

    // ---- layer 4 (only the lower bound matters for the output) ----
    k_affine_interval<<<(DOUT + 7) / 8, 256>>>(w4, b4, PUB + 2 * H, PLB + 2 * H,
                                               UB4, LB4, H, DOUT);
    descend(w4, b4, DOUT, 0, 3, nullptr, LB4, nullptr);

    k_final_min<<<1, 32>>>(LB4, out);
}